// round 11
// baseline (speedup 1.0000x reference)
#include <cuda_runtime.h>
#include <cuda_fp16.h>
#include <cstdint>

// Problem constants
#define BB 8
#define NN 2048
#define CC 1024
#define HH 16
#define DD 64
#define MM (BB * NN)        // 16384 rows
#define K3 (3 * CC)         // 3072
#define KER 5
#define QK2 (2 * CC)        // 2048 (q|k f32 row width)

// GEMM tiling: block 256x128, warp tile 64x64, BK=64 halves, 3-stage cp.async
#define BKH 64                        // K halves per stage = 128 B/row
#define HSTRIDE 144                   // smem row stride bytes (72 halves, conflict-free)
#define ATILE (256 * HSTRIDE)         // 36864
#define BTILE (128 * HSTRIDE)         // 18432
#define STG (ATILE + BTILE)           // 55296
#define NSTG 3
#define GEMM_SMEM (NSTG * STG)        // 165888

#define KVSPLIT 8
#define BFSPLIT 16

// ---------------------------------------------------------------------------
// Scratch (device globals; no allocations allowed)
// ---------------------------------------------------------------------------
__device__ float  g_qk[(size_t)MM * QK2];       // q|k f32 (pre-focus), row width 2048
__device__ __half g_vh[(size_t)MM * CC];        // v half
__device__ __half g_qh[(size_t)MM * CC];        // q half (post-focus)
__device__ __half g_kh[(size_t)MM * CC];        // k half (post-focus)
__device__ __half g_oh[(size_t)MM * CC];        // attention+dwc (half, proj A operand)
__device__ __half g_xh[(size_t)MM * CC];        // x in half
__device__ __half g_whq[(size_t)K3 * CC];       // (a ⊙ W_qkv)^T half
__device__ __half g_whp[(size_t)CC * CC];       // W_proj^T half
__device__ float  g_kv[BB * HH * DD * DD];
__device__ float  g_ksum[BB * HH * DD];
__device__ float  g_kvp[(size_t)BB * HH * KVSPLIT * DD * DD];
__device__ float  g_ksp[BB * HH * KVSPLIT * DD];
__device__ float  g_part[256 * 2 * CC];
__device__ float  g_bp[BFSPLIT * K3];
__device__ float  g_a[CC], g_shift[CC], g_scale[CC];
__device__ float  g_bias2[K3];                  // b_qkv + shift @ W_qkv

// ---------------------------------------------------------------------------
// PTX helpers
// ---------------------------------------------------------------------------
__device__ __forceinline__ uint32_t smem_u32(const void* p) {
    uint32_t a;
    asm("{ .reg .u64 t; cvta.to.shared.u64 t, %1; cvt.u32.u64 %0, t; }" : "=r"(a) : "l"(p));
    return a;
}
__device__ __forceinline__ void cp_async16(uint32_t saddr, const void* gptr) {
    asm volatile("cp.async.cg.shared.global [%0], [%1], 16;" :: "r"(saddr), "l"(gptr) : "memory");
}
__device__ __forceinline__ void cp_commit() {
    asm volatile("cp.async.commit_group;" ::: "memory");
}
template <int N>
__device__ __forceinline__ void cp_wait() {
    asm volatile("cp.async.wait_group %0;" :: "n"(N) : "memory");
}
__device__ __forceinline__ void ldm_x4(uint32_t* r, uint32_t addr) {
    asm volatile("ldmatrix.sync.aligned.m8n8.x4.shared.b16 {%0,%1,%2,%3}, [%4];"
                 : "=r"(r[0]), "=r"(r[1]), "=r"(r[2]), "=r"(r[3]) : "r"(addr));
}
__device__ __forceinline__ void mma_f16(float* c, const uint32_t* a, const uint32_t* b) {
    asm volatile(
        "mma.sync.aligned.m16n8k16.row.col.f32.f16.f16.f32 "
        "{%0,%1,%2,%3}, {%4,%5,%6,%7}, {%8,%9}, {%0,%1,%2,%3};"
        : "+f"(c[0]), "+f"(c[1]), "+f"(c[2]), "+f"(c[3])
        : "r"(a[0]), "r"(a[1]), "r"(a[2]), "r"(a[3]), "r"(b[0]), "r"(b[1]));
}

// ---------------------------------------------------------------------------
// BN stats partial sums fused with x -> half conversion.
// ---------------------------------------------------------------------------
__global__ void __launch_bounds__(256) bnf2h_kernel(const float* __restrict__ x,
                                                    __half* __restrict__ xh) {
    const int blk = blockIdx.x;
    const int tid = threadIdx.x;
    const int r0 = blk * 64;
    float s[4] = {0.f, 0.f, 0.f, 0.f};
    float ss[4] = {0.f, 0.f, 0.f, 0.f};
    for (int r = 0; r < 64; ++r) {
        const size_t rowo = (size_t)(r0 + r) * CC;
        float4 v = *(const float4*)(x + rowo + tid * 4);
        s[0] += v.x; ss[0] += v.x * v.x;
        s[1] += v.y; ss[1] += v.y * v.y;
        s[2] += v.z; ss[2] += v.z * v.z;
        s[3] += v.w; ss[3] += v.w * v.w;
        __half2 h0 = __floats2half2_rn(v.x, v.y);
        __half2 h1 = __floats2half2_rn(v.z, v.w);
        uint2 u;
        u.x = *(uint32_t*)&h0; u.y = *(uint32_t*)&h1;
        *(uint2*)(xh + rowo + tid * 4) = u;
    }
#pragma unroll
    for (int j = 0; j < 4; ++j) {
        g_part[(size_t)blk * 2048 + tid * 4 + j] = s[j];
        g_part[(size_t)blk * 2048 + 1024 + tid * 4 + j] = ss[j];
    }
}

__global__ void bn_finalize_kernel(const float* __restrict__ gamma,
                                   const float* __restrict__ beta,
                                   const float* __restrict__ scale_p) {
    const int ch = blockIdx.x * 256 + threadIdx.x;
    float s = 0.f, ss = 0.f;
    for (int b = 0; b < 256; ++b) {
        s += g_part[(size_t)b * 2048 + ch];
        ss += g_part[(size_t)b * 2048 + 1024 + ch];
    }
    const float inv = 1.0f / (float)MM;
    float mean = s * inv;
    float var = ss * inv - mean * mean;
    float rstd = rsqrtf(var + 1e-5f);
    float a = rstd * gamma[ch];
    g_a[ch] = a;
    g_shift[ch] = beta[ch] - mean * a;
    float p = scale_p[ch];
    g_scale[ch] = fmaxf(p, 0.f) + log1pf(expf(-fabsf(p)));
}

// ---------------------------------------------------------------------------
// Transpose W (K,N) -> Wt (N,K) half; SCALE folds g_a[k] (BN).
// ---------------------------------------------------------------------------
template <bool SCALE>
__global__ void __launch_bounds__(256) transpose_h_kernel(
    const float* __restrict__ W, __half* __restrict__ Wt, int K, int N)
{
    __shared__ float t[32][33];
    const int n0 = blockIdx.x * 32, k0 = blockIdx.y * 32;
    const int tx = threadIdx.x & 31, ty = threadIdx.x >> 5;
#pragma unroll
    for (int i = 0; i < 4; ++i)
        t[ty + i * 8][tx] = W[(size_t)(k0 + ty + i * 8) * N + n0 + tx];
    __syncthreads();
    const float ak = SCALE ? g_a[k0 + tx] : 1.0f;
#pragma unroll
    for (int i = 0; i < 4; ++i)
        Wt[(size_t)(n0 + ty + i * 8) * K + k0 + tx] = __float2half_rn(ak * t[tx][ty + i * 8]);
}

// ---------------------------------------------------------------------------
// Fold BN shift into qkv bias (split-K): part c covers k in [c*64, c*64+64)
// ---------------------------------------------------------------------------
__global__ void __launch_bounds__(256) biasfold_part_kernel(const float* __restrict__ W) {
    const int n = blockIdx.x * 256 + threadIdx.x;
    const int c = blockIdx.y;
    float s = 0.f;
    const int k0 = c * (CC / BFSPLIT);
#pragma unroll 8
    for (int k = 0; k < CC / BFSPLIT; ++k)
        s += g_shift[k0 + k] * W[(size_t)(k0 + k) * K3 + n];
    g_bp[(size_t)c * K3 + n] = s;
}
__global__ void __launch_bounds__(256) biasfold_reduce_kernel(const float* __restrict__ b) {
    const int n = blockIdx.x * 256 + threadIdx.x;
    float s = b[n];
#pragma unroll
    for (int c = 0; c < BFSPLIT; ++c)
        s += g_bp[(size_t)c * K3 + n];
    g_bias2[n] = s;
}

// ---------------------------------------------------------------------------
// fp16 mma.sync GEMM: C[m,n] = sum_k A[m,k]*Bt[n,k] + bias[n]  (f32 accum)
// Block 256x128, BK=64 halves, 8 warps (4m x 2n), warp tile 64x64, 3-stage
// cp.async, ldmatrix.x4 fragment loads (ratio 4 MMA per ldmatrix).
// SPLIT: cols < 2048 -> f32 to Cf (stride strideF); cols >= 2048 -> half to Ch.
// ---------------------------------------------------------------------------
template <bool SPLIT>
__global__ void __launch_bounds__(256, 1) gemm_hmma(
    const __half* __restrict__ A, const __half* __restrict__ Bt,
    const float* __restrict__ bias, float* __restrict__ Cf, int strideF,
    __half* __restrict__ Ch, int Ndim, int Kdim)
{
    extern __shared__ char sm[];
    const int tid = threadIdx.x;
    const int lane = tid & 31, w = tid >> 5;
    const int wm = w & 3, wn = w >> 2;
    const int row0 = blockIdx.y * 256, col0 = blockIdx.x * 128;
    const uint32_t sbase = smem_u32(sm);

    // cp.async loader: thread t -> row t>>1 (and +128 for A), 64B half (t&1)
    const int lrow = tid >> 1, lh = tid & 1;
    const __half* gA = A + (size_t)(row0 + lrow) * Kdim + lh * 32;
    const __half* gB = Bt + (size_t)(col0 + lrow) * Kdim + lh * 32;
    const uint32_t sOff = (uint32_t)(lrow * HSTRIDE + lh * 64);

    float acc[4][8][4];
#pragma unroll
    for (int mi = 0; mi < 4; ++mi)
#pragma unroll
        for (int ni = 0; ni < 8; ++ni)
#pragma unroll
            for (int j = 0; j < 4; ++j) acc[mi][ni][j] = 0.f;

    const uint32_t aoff0 = (uint32_t)((wm * 64 + (lane & 15)) * HSTRIDE + (lane >> 4) * 16);
    const uint32_t boff0 = (uint32_t)((wn * 64 + (lane & 7) + (lane >> 4) * 8) * HSTRIDE +
                                      ((lane >> 3) & 1) * 16);

    const int T = Kdim / BKH;

    // prologue: stages 0, 1
#pragma unroll
    for (int s = 0; s < 2; ++s) {
        const uint32_t sa = sbase + s * STG + sOff;
        const uint32_t sb = sbase + s * STG + ATILE + sOff;
        const __half* ga = gA + s * BKH;
        const __half* gb = gB + s * BKH;
#pragma unroll
        for (int i = 0; i < 4; ++i) {
            cp_async16(sa + i * 16, ga + i * 8);
            cp_async16(sa + 128 * HSTRIDE + i * 16, ga + (size_t)128 * Kdim + i * 8);
            cp_async16(sb + i * 16, gb + i * 8);
        }
        cp_commit();
    }

    for (int t = 0; t < T; ++t) {
        if (t == T - 1) cp_wait<0>(); else cp_wait<1>();
        __syncthreads();
        if (t + 2 < T) {
            const int sidx = (t + 2) % NSTG;
            const uint32_t sa = sbase + sidx * STG + sOff;
            const uint32_t sb = sbase + sidx * STG + ATILE + sOff;
            const __half* ga = gA + (t + 2) * BKH;
            const __half* gb = gB + (t + 2) * BKH;
#pragma unroll
            for (int i = 0; i < 4; ++i) {
                cp_async16(sa + i * 16, ga + i * 8);
                cp_async16(sa + 128 * HSTRIDE + i * 16, ga + (size_t)128 * Kdim + i * 8);
                cp_async16(sb + i * 16, gb + i * 8);
            }
            cp_commit();
        }
        const int buf = t % NSTG;
        const uint32_t abase = sbase + buf * STG + aoff0;
        const uint32_t bbase = sbase + buf * STG + ATILE + boff0;
#pragma unroll
        for (int ks = 0; ks < 4; ++ks) {
            uint32_t af[4][4];
            uint32_t bf[4][4];
#pragma unroll
            for (int mi = 0; mi < 4; ++mi)
                ldm_x4(af[mi], abase + mi * 16 * HSTRIDE + ks * 32);
#pragma unroll
            for (int nt = 0; nt < 4; ++nt)
                ldm_x4(bf[nt], bbase + nt * 16 * HSTRIDE + ks * 32);
#pragma unroll
            for (int mi = 0; mi < 4; ++mi)
#pragma unroll
                for (int ni = 0; ni < 8; ++ni)
                    mma_f16(acc[mi][ni], af[mi], &bf[ni >> 1][(ni & 1) * 2]);
        }
    }
    __syncthreads();

    // epilogue
    const int lr = lane >> 2, lc = lane & 3;
    const float* brow = bias + col0 + wn * 64;
    const bool vmode = SPLIT && (col0 >= QK2);
#pragma unroll
    for (int mi = 0; mi < 4; ++mi) {
        const int mrow = row0 + wm * 64 + mi * 16 + lr;
#pragma unroll
        for (int hf = 0; hf < 2; ++hf) {
            const int r = mrow + hf * 8;
            if (!vmode) {
                float* Cr = Cf + (size_t)r * strideF + col0 + wn * 64;
#pragma unroll
                for (int ni = 0; ni < 8; ++ni) {
                    float2 o;
                    o.x = acc[mi][ni][hf * 2 + 0] + brow[ni * 8 + 2 * lc];
                    o.y = acc[mi][ni][hf * 2 + 1] + brow[ni * 8 + 2 * lc + 1];
                    *(float2*)(Cr + ni * 8 + 2 * lc) = o;
                }
            } else {
                __half* Hr = Ch + (size_t)r * CC + (col0 - QK2) + wn * 64;
#pragma unroll
                for (int ni = 0; ni < 8; ++ni) {
                    float ox = acc[mi][ni][hf * 2 + 0] + brow[ni * 8 + 2 * lc];
                    float oy = acc[mi][ni][hf * 2 + 1] + brow[ni * 8 + 2 * lc + 1];
                    *(__half2*)(Hr + ni * 8 + 2 * lc) = __floats2half2_rn(ox, oy);
                }
            }
        }
    }
}

// ---------------------------------------------------------------------------
// Focus: t=(relu+1e-6)/scale; out = t^3 * ||t|| / ||t^3||; q,k f32 -> half
// ---------------------------------------------------------------------------
__device__ __forceinline__ float block_sum256(float v, float* sh) {
    const int lane = threadIdx.x & 31, w = threadIdx.x >> 5;
#pragma unroll
    for (int o = 16; o; o >>= 1) v += __shfl_xor_sync(0xffffffffu, v, o);
    if (lane == 0) sh[w] = v;
    __syncthreads();
    if (w == 0) {
        float t = (lane < 8) ? sh[lane] : 0.f;
#pragma unroll
        for (int o = 4; o; o >>= 1) t += __shfl_xor_sync(0xffffffffu, t, o);
        if (lane == 0) sh[0] = t;
    }
    __syncthreads();
    float r = sh[0];
    __syncthreads();
    return r;
}

__global__ void __launch_bounds__(256) focus_kernel() {
    __shared__ float sh[8];
    const int row = blockIdx.x;
    const int tid = threadIdx.x;
    float4 sc4 = *(const float4*)&g_scale[tid * 4];
    const float scl[4] = {sc4.x, sc4.y, sc4.z, sc4.w};

#pragma unroll
    for (int seg = 0; seg < 2; ++seg) {
        const float* base = g_qk + (size_t)row * QK2 + seg * CC;
        __half* outp = (seg == 0 ? g_qh : g_kh) + (size_t)row * CC;
        float4 vv = *(const float4*)(base + tid * 4);
        float t[4];
        t[0] = (fmaxf(vv.x, 0.f) + 1e-6f) / scl[0];
        t[1] = (fmaxf(vv.y, 0.f) + 1e-6f) / scl[1];
        t[2] = (fmaxf(vv.z, 0.f) + 1e-6f) / scl[2];
        t[3] = (fmaxf(vv.w, 0.f) + 1e-6f) / scl[3];
        float s1 = t[0] * t[0] + t[1] * t[1] + t[2] * t[2] + t[3] * t[3];
        float n1sq = block_sum256(s1, sh);
        float u[4];
        float s2 = 0.f;
#pragma unroll
        for (int i = 0; i < 4; ++i) {
            u[i] = t[i] * t[i] * t[i];
            s2 += u[i] * u[i];
        }
        float n3sq = block_sum256(s2, sh);
        float r = sqrtf(n1sq) * rsqrtf(n3sq);
        __half2 h0 = __floats2half2_rn(u[0] * r, u[1] * r);
        __half2 h1 = __floats2half2_rn(u[2] * r, u[3] * r);
        uint2 uo;
        uo.x = *(uint32_t*)&h0; uo.y = *(uint32_t*)&h1;
        *(uint2*)(outp + tid * 4) = uo;
    }
}

// ---------------------------------------------------------------------------
// Per-head partial kv = K^T V and ksum over a slice of N. grid (B*H, KVSPLIT).
// ---------------------------------------------------------------------------
__global__ void __launch_bounds__(256) kv_part_kernel() {
    const int bh = blockIdx.x;
    const int chunk = blockIdx.y;
    const int b = bh >> 4, h = bh & 15;
    __shared__ float Ks[64][68];
    __shared__ float Vs[64][68];
    __shared__ float kred[4][64];
    const int tid = threadIdx.x;
    const int tr = tid >> 4, tc = tid & 15;
    const int lr = tid >> 4;
    const int lc4 = (tid & 15) * 4;

    float acc[4][4];
#pragma unroll
    for (int i = 0; i < 4; ++i)
#pragma unroll
        for (int j = 0; j < 4; ++j) acc[i][j] = 0.f;
    float kpart = 0.f;
    const int scol = tid & 63, srg = tid >> 6;

    const int nlo = chunk * (NN / KVSPLIT);
    const int nhi = nlo + (NN / KVSPLIT);

    for (int n0 = nlo; n0 < nhi; n0 += 64) {
#pragma unroll
        for (int i = 0; i < 4; ++i) {
            const int r = lr + i * 16;
            const size_t off = (size_t)(b * NN + n0 + r) * CC + h * DD + lc4;
            uint2 uk = *(const uint2*)(g_kh + off);
            uint2 uv = *(const uint2*)(g_vh + off);
            float2 k01 = __half22float2(*(__half2*)&uk.x);
            float2 k23 = __half22float2(*(__half2*)&uk.y);
            float2 v01 = __half22float2(*(__half2*)&uv.x);
            float2 v23 = __half22float2(*(__half2*)&uv.y);
            Ks[r][lc4 + 0] = k01.x; Ks[r][lc4 + 1] = k01.y;
            Ks[r][lc4 + 2] = k23.x; Ks[r][lc4 + 3] = k23.y;
            Vs[r][lc4 + 0] = v01.x; Vs[r][lc4 + 1] = v01.y;
            Vs[r][lc4 + 2] = v23.x; Vs[r][lc4 + 3] = v23.y;
        }
        __syncthreads();
#pragma unroll
        for (int kk = 0; kk < 64; ++kk) {
            float ra[4], rbv[4];
#pragma unroll
            for (int i = 0; i < 4; ++i) {
                ra[i] = Ks[kk][tr * 4 + i];
                rbv[i] = Vs[kk][tc * 4 + i];
            }
#pragma unroll
            for (int i = 0; i < 4; ++i)
#pragma unroll
                for (int j = 0; j < 4; ++j)
                    acc[i][j] = fmaf(ra[i], rbv[j], acc[i][j]);
        }
#pragma unroll
        for (int r = 0; r < 16; ++r) kpart += Ks[srg * 16 + r][scol];
        __syncthreads();
    }
    kred[srg][scol] = kpart;
    __syncthreads();
    const size_t pb = (size_t)(bh * KVSPLIT + chunk);
    if (tid < 64)
        g_ksp[pb * DD + tid] = kred[0][tid] + kred[1][tid] + kred[2][tid] + kred[3][tid];
#pragma unroll
    for (int i = 0; i < 4; ++i)
#pragma unroll
        for (int j = 0; j < 4; ++j)
            g_kvp[pb * 4096 + (tr * 4 + i) * 64 + tc * 4 + j] = acc[i][j];
}

__global__ void __launch_bounds__(256) kv_reduce_kernel() {
    const int bh = blockIdx.x;
    const int tid = threadIdx.x;
    for (int idx = tid; idx < 4096; idx += 256) {
        float s = 0.f;
#pragma unroll
        for (int c = 0; c < KVSPLIT; ++c)
            s += g_kvp[(size_t)(bh * KVSPLIT + c) * 4096 + idx];
        g_kv[(size_t)bh * 4096 + idx] = s;
    }
    if (tid < 64) {
        float s = 0.f;
#pragma unroll
        for (int c = 0; c < KVSPLIT; ++c)
            s += g_ksp[(size_t)(bh * KVSPLIT + c) * DD + tid];
        g_ksum[bh * DD + tid] = s;
    }
}

// ---------------------------------------------------------------------------
// Fused: o = (q @ kv) * z + depthwise-conv5(v) + dwc bias; writes half g_oh.
// ---------------------------------------------------------------------------
__global__ void __launch_bounds__(256) o_dwc_kernel(const float* __restrict__ w,
                                                    const float* __restrict__ bias) {
    const int bh = blockIdx.y;
    const int b = bh >> 4, h = bh & 15;
    const int n0 = blockIdx.x * 64;
    __shared__ float kvs[64][65];
    __shared__ float ks[64];
    __shared__ uint4 vsl4[68][8];   // v slice [n0-2, n0+66) x 64 ch (half)
    const int tid = threadIdx.x;
    const int lane = tid & 31, warp = tid >> 5;

    for (int idx = tid; idx < 4096; idx += 256)
        kvs[idx >> 6][idx & 63] = g_kv[(size_t)bh * 4096 + idx];
    if (tid < 64) ks[tid] = g_ksum[bh * DD + tid];
    for (int idx = tid; idx < 68 * 8; idx += 256) {
        const int row = idx >> 3, seg = idx & 7;
        const int n = n0 - 2 + row;
        uint4 val = make_uint4(0u, 0u, 0u, 0u);
        if (n >= 0 && n < NN)
            val = *(const uint4*)(g_vh + (size_t)(b * NN + n) * CC + h * DD + seg * 8);
        vsl4[row][seg] = val;
    }
    __syncthreads();
    const __half* vs = (const __half*)vsl4;   // [68][64]

    const int c1 = h * DD + lane, c2 = c1 + 32;
    float w1[5], w2[5];
#pragma unroll
    for (int j = 0; j < 5; ++j) { w1[j] = w[c1 * KER + j]; w2[j] = w[c2 * KER + j]; }
    const float b1 = bias[c1], b2 = bias[c2];

    for (int rr = 0; rr < 8; ++rr) {
        const int li = warp * 8 + rr;
        const int n = n0 + li;
        const size_t gr = (size_t)(b * NN + n);
        const __half* qrow = g_qh + gr * CC + h * DD;
        float qa = __half2float(qrow[lane]);
        float qb = __half2float(qrow[lane + 32]);
        float zp = qa * ks[lane] + qb * ks[lane + 32];
#pragma unroll
        for (int o = 16; o; o >>= 1) zp += __shfl_xor_sync(0xffffffffu, zp, o);
        float z = 1.0f / (zp + 1e-6f);
        float o1 = 0.f, o2 = 0.f;
#pragma unroll
        for (int d = 0; d < 32; ++d) {
            float qd = __shfl_sync(0xffffffffu, qa, d);
            o1 = fmaf(qd, kvs[d][lane], o1);
            o2 = fmaf(qd, kvs[d][lane + 32], o2);
        }
#pragma unroll
        for (int d = 0; d < 32; ++d) {
            float qd = __shfl_sync(0xffffffffu, qb, d);
            o1 = fmaf(qd, kvs[d + 32][lane], o1);
            o2 = fmaf(qd, kvs[d + 32][lane + 32], o2);
        }
        float d1 = b1, d2 = b2;
#pragma unroll
        for (int j = 0; j < 5; ++j) {
            d1 = fmaf(w1[j], __half2float(vs[(li + j) * 64 + lane]), d1);
            d2 = fmaf(w2[j], __half2float(vs[(li + j) * 64 + lane + 32]), d2);
        }
        __half* orow = g_oh + gr * CC + h * DD;
        orow[lane] = __float2half_rn(fmaf(o1, z, d1));
        orow[lane + 32] = __float2half_rn(fmaf(o2, z, d2));
    }
}

// ---------------------------------------------------------------------------
// Launch
// ---------------------------------------------------------------------------
extern "C" void kernel_launch(void* const* d_in, const int* in_sizes, int n_in,
                              void* d_out, int out_size) {
    const float* x       = (const float*)d_in[0];
    const float* gamma   = (const float*)d_in[1];
    const float* beta    = (const float*)d_in[2];
    const float* Wqkv    = (const float*)d_in[3];
    const float* bqkv    = (const float*)d_in[4];
    const float* scale_p = (const float*)d_in[5];
    const float* dwc_w   = (const float*)d_in[6];
    const float* dwc_b   = (const float*)d_in[7];
    const float* Wproj   = (const float*)d_in[8];
    const float* bproj   = (const float*)d_in[9];
    float* out = (float*)d_out;

    float*  qk_ptr;  cudaGetSymbolAddress((void**)&qk_ptr, g_qk);
    __half* vh_ptr;  cudaGetSymbolAddress((void**)&vh_ptr, g_vh);
    __half* xh_ptr;  cudaGetSymbolAddress((void**)&xh_ptr, g_xh);
    __half* whq_ptr; cudaGetSymbolAddress((void**)&whq_ptr, g_whq);
    __half* whp_ptr; cudaGetSymbolAddress((void**)&whp_ptr, g_whp);
    __half* oh_ptr;  cudaGetSymbolAddress((void**)&oh_ptr, g_oh);
    float*  b2_ptr;  cudaGetSymbolAddress((void**)&b2_ptr, g_bias2);

    cudaFuncSetAttribute(gemm_hmma<true>,  cudaFuncAttributeMaxDynamicSharedMemorySize, GEMM_SMEM);
    cudaFuncSetAttribute(gemm_hmma<false>, cudaFuncAttributeMaxDynamicSharedMemorySize, GEMM_SMEM);

    // 1. BN statistics (fused with x -> half)
    bnf2h_kernel<<<256, 256>>>(x, xh_ptr);
    bn_finalize_kernel<<<4, 256>>>(gamma, beta, scale_p);

    // 2. Weights -> transposed half (BN scale folded into Wqkv); shift -> bias (split-K).
    transpose_h_kernel<true><<<dim3(K3 / 32, CC / 32), 256>>>(Wqkv, whq_ptr, CC, K3);
    transpose_h_kernel<false><<<dim3(CC / 32, CC / 32), 256>>>(Wproj, whp_ptr, CC, CC);
    biasfold_part_kernel<<<dim3(K3 / 256, BFSPLIT), 256>>>(Wqkv);
    biasfold_reduce_kernel<<<K3 / 256, 256>>>(bqkv);

    // 3. QKV GEMM: q,k -> f32 g_qk; v -> half g_vh (split epilogue)
    gemm_hmma<true><<<dim3(K3 / 128, MM / 256), 256, GEMM_SMEM>>>(
        xh_ptr, whq_ptr, b2_ptr, qk_ptr, QK2, vh_ptr, K3, CC);

    // 4. Focused feature map: q,k f32 -> half g_qh/g_kh
    focus_kernel<<<MM, 256>>>();

    // 5. Per-head kv = K^T V and ksum (split over N, then reduce)
    kv_part_kernel<<<dim3(BB * HH, KVSPLIT), 256>>>();
    kv_reduce_kernel<<<BB * HH, 256>>>();

    // 6. Fused attention output + depthwise conv -> half g_oh
    o_dwc_kernel<<<dim3(NN / 64, BB * HH), 256>>>(dwc_w, dwc_b);

    // 7. Projection GEMM (f32 out)
    gemm_hmma<false><<<dim3(CC / 128, MM / 256), 256, GEMM_SMEM>>>(
        oh_ptr, whp_ptr, bproj, out, CC, (__half*)nullptr, CC, CC);
}

// round 12
// speedup vs baseline: 1.0763x; 1.0763x over previous
#include <cuda_runtime.h>
#include <cuda_fp16.h>
#include <cstdint>

// Problem constants
#define BB 8
#define NN 2048
#define CC 1024
#define HH 16
#define DD 64
#define MM (BB * NN)        // 16384 rows
#define K3 (3 * CC)         // 3072
#define KER 5
#define QK2 (2 * CC)        // 2048

// GEMM tiling (fp16 mma.sync m16n8k16 + ldmatrix, 3-stage cp.async) — R9 config
#define BKH 64                        // K halves per stage = 128 B/row
#define HSTRIDE 144                   // smem row stride bytes (72 halves, conflict-free)
#define HTILE (128 * HSTRIDE)         // 18432 per operand tile
#define HSTAGE (2 * HTILE)            // A + B = 36864
#define NSTG 3
#define GEMM_SMEM3 (NSTG * HSTAGE)    // 110592

#define KVSPLIT 8
#define BFSPLIT 16

// ---------------------------------------------------------------------------
// Scratch (device globals; no allocations allowed)
// ---------------------------------------------------------------------------
__device__ __half g_vh[(size_t)MM * CC];        // v half
__device__ __half g_qh[(size_t)MM * CC];        // q "t" half (pre-cube focus val)
__device__ __half g_kh[(size_t)MM * CC];        // k "t" half
__device__ __half g_oh[(size_t)MM * CC];        // attention+dwc (half, proj A operand)
__device__ __half g_xh[(size_t)MM * CC];        // x in half
__device__ __half g_whq[(size_t)K3 * CC];       // (a ⊙ W_qkv)^T half
__device__ __half g_whp[(size_t)CC * CC];       // W_proj^T half
__device__ float2 g_fq[(size_t)MM * 16];        // q row partials (sum t^2, sum t^6)
__device__ float2 g_fk[(size_t)MM * 16];        // k row partials
__device__ float  g_r[2 * MM];                  // per-row focus factor (q then k)
__device__ float  g_kv[BB * HH * DD * DD];
__device__ float  g_ksum[BB * HH * DD];
__device__ float  g_kvp[(size_t)BB * HH * KVSPLIT * DD * DD];
__device__ float  g_ksp[BB * HH * KVSPLIT * DD];
__device__ float  g_part[256 * 2 * CC];
__device__ float  g_bp[BFSPLIT * K3];
__device__ float  g_a[CC], g_shift[CC], g_scale[CC];
__device__ float  g_bias2[K3];                  // b_qkv + shift @ W_qkv

// ---------------------------------------------------------------------------
// PTX helpers
// ---------------------------------------------------------------------------
__device__ __forceinline__ uint32_t smem_u32(const void* p) {
    uint32_t a;
    asm("{ .reg .u64 t; cvta.to.shared.u64 t, %1; cvt.u32.u64 %0, t; }" : "=r"(a) : "l"(p));
    return a;
}
__device__ __forceinline__ void cp_async16(uint32_t saddr, const void* gptr) {
    asm volatile("cp.async.cg.shared.global [%0], [%1], 16;" :: "r"(saddr), "l"(gptr) : "memory");
}
__device__ __forceinline__ void cp_commit() {
    asm volatile("cp.async.commit_group;" ::: "memory");
}
template <int N>
__device__ __forceinline__ void cp_wait() {
    asm volatile("cp.async.wait_group %0;" :: "n"(N) : "memory");
}
__device__ __forceinline__ void ldm_x4(uint32_t* r, uint32_t addr) {
    asm volatile("ldmatrix.sync.aligned.m8n8.x4.shared.b16 {%0,%1,%2,%3}, [%4];"
                 : "=r"(r[0]), "=r"(r[1]), "=r"(r[2]), "=r"(r[3]) : "r"(addr));
}
__device__ __forceinline__ void mma_f16(float* c, const uint32_t* a, const uint32_t* b) {
    asm volatile(
        "mma.sync.aligned.m16n8k16.row.col.f32.f16.f16.f32 "
        "{%0,%1,%2,%3}, {%4,%5,%6,%7}, {%8,%9}, {%0,%1,%2,%3};"
        : "+f"(c[0]), "+f"(c[1]), "+f"(c[2]), "+f"(c[3])
        : "r"(a[0]), "r"(a[1]), "r"(a[2]), "r"(a[3]), "r"(b[0]), "r"(b[1]));
}

// ---------------------------------------------------------------------------
// BN stats partial sums fused with x -> half conversion.
// ---------------------------------------------------------------------------
__global__ void __launch_bounds__(256) bnf2h_kernel(const float* __restrict__ x,
                                                    __half* __restrict__ xh) {
    const int blk = blockIdx.x;
    const int tid = threadIdx.x;
    const int r0 = blk * 64;
    float s[4] = {0.f, 0.f, 0.f, 0.f};
    float ss[4] = {0.f, 0.f, 0.f, 0.f};
    for (int r = 0; r < 64; ++r) {
        const size_t rowo = (size_t)(r0 + r) * CC;
        float4 v = *(const float4*)(x + rowo + tid * 4);
        s[0] += v.x; ss[0] += v.x * v.x;
        s[1] += v.y; ss[1] += v.y * v.y;
        s[2] += v.z; ss[2] += v.z * v.z;
        s[3] += v.w; ss[3] += v.w * v.w;
        __half2 h0 = __floats2half2_rn(v.x, v.y);
        __half2 h1 = __floats2half2_rn(v.z, v.w);
        uint2 u;
        u.x = *(uint32_t*)&h0; u.y = *(uint32_t*)&h1;
        *(uint2*)(xh + rowo + tid * 4) = u;
    }
#pragma unroll
    for (int j = 0; j < 4; ++j) {
        g_part[(size_t)blk * 2048 + tid * 4 + j] = s[j];
        g_part[(size_t)blk * 2048 + 1024 + tid * 4 + j] = ss[j];
    }
}

__global__ void bn_finalize_kernel(const float* __restrict__ gamma,
                                   const float* __restrict__ beta,
                                   const float* __restrict__ scale_p) {
    const int ch = blockIdx.x * 256 + threadIdx.x;
    float s = 0.f, ss = 0.f;
    for (int b = 0; b < 256; ++b) {
        s += g_part[(size_t)b * 2048 + ch];
        ss += g_part[(size_t)b * 2048 + 1024 + ch];
    }
    const float inv = 1.0f / (float)MM;
    float mean = s * inv;
    float var = ss * inv - mean * mean;
    float rstd = rsqrtf(var + 1e-5f);
    float a = rstd * gamma[ch];
    g_a[ch] = a;
    g_shift[ch] = beta[ch] - mean * a;
    float p = scale_p[ch];
    g_scale[ch] = fmaxf(p, 0.f) + log1pf(expf(-fabsf(p)));
}

// ---------------------------------------------------------------------------
// Transpose W (K,N) -> Wt (N,K) half; SCALE folds g_a[k] (BN).
// ---------------------------------------------------------------------------
template <bool SCALE>
__global__ void __launch_bounds__(256) transpose_h_kernel(
    const float* __restrict__ W, __half* __restrict__ Wt, int K, int N)
{
    __shared__ float t[32][33];
    const int n0 = blockIdx.x * 32, k0 = blockIdx.y * 32;
    const int tx = threadIdx.x & 31, ty = threadIdx.x >> 5;
#pragma unroll
    for (int i = 0; i < 4; ++i)
        t[ty + i * 8][tx] = W[(size_t)(k0 + ty + i * 8) * N + n0 + tx];
    __syncthreads();
    const float ak = SCALE ? g_a[k0 + tx] : 1.0f;
#pragma unroll
    for (int i = 0; i < 4; ++i)
        Wt[(size_t)(n0 + ty + i * 8) * K + k0 + tx] = __float2half_rn(ak * t[tx][ty + i * 8]);
}

// ---------------------------------------------------------------------------
// Fold BN shift into qkv bias (split-K) + reduce
// ---------------------------------------------------------------------------
__global__ void __launch_bounds__(256) biasfold_part_kernel(const float* __restrict__ W) {
    const int n = blockIdx.x * 256 + threadIdx.x;
    const int c = blockIdx.y;
    float s = 0.f;
    const int k0 = c * (CC / BFSPLIT);
#pragma unroll 8
    for (int k = 0; k < CC / BFSPLIT; ++k)
        s += g_shift[k0 + k] * W[(size_t)(k0 + k) * K3 + n];
    g_bp[(size_t)c * K3 + n] = s;
}
__global__ void __launch_bounds__(256) biasfold_reduce_kernel(const float* __restrict__ b) {
    const int n = blockIdx.x * 256 + threadIdx.x;
    float s = b[n];
#pragma unroll
    for (int c = 0; c < BFSPLIT; ++c)
        s += g_bp[(size_t)c * K3 + n];
    g_bias2[n] = s;
}

// ---------------------------------------------------------------------------
// fp16 mma.sync GEMM. Block 128x128, BK=64, 8 warps (4m x 2n), warp 32x64,
// 3-stage cp.async.
// SPLIT (QKV): cols <  CC   -> focus-t half to g_qh + row partials g_fq
//              cols <  QK2  -> focus-t half to g_kh + row partials g_fk
//              cols >= QK2  -> plain half to g_vh
// !SPLIT (proj): f32 to Cf.
// ---------------------------------------------------------------------------
template <bool SPLIT>
__global__ void __launch_bounds__(256, 2) gemm_hmma(
    const __half* __restrict__ A, const __half* __restrict__ Bt,
    const float* __restrict__ bias, float* __restrict__ Cf,
    int Ndim, int Kdim)
{
    extern __shared__ char sm[];
    const int tid = threadIdx.x;
    const int lane = tid & 31, w = tid >> 5;
    const int wm = w & 3, wn = w >> 2;
    const int row0 = blockIdx.y * 128, col0 = blockIdx.x * 128;
    const uint32_t sbase = smem_u32(sm);

    const int lrow = tid >> 1, lh = tid & 1;
    const __half* gA = A + (size_t)(row0 + lrow) * Kdim + lh * 32;
    const __half* gB = Bt + (size_t)(col0 + lrow) * Kdim + lh * 32;
    const uint32_t sOff = (uint32_t)(lrow * HSTRIDE + lh * 64);

    float acc[2][8][4];
#pragma unroll
    for (int mi = 0; mi < 2; ++mi)
#pragma unroll
        for (int ni = 0; ni < 8; ++ni)
#pragma unroll
            for (int j = 0; j < 4; ++j) acc[mi][ni][j] = 0.f;

    const uint32_t aoff0 = (uint32_t)((wm * 32 + (lane & 15)) * HSTRIDE + (lane >> 4) * 16);
    const uint32_t boff0 = (uint32_t)((wn * 64 + (lane & 7) + (lane >> 4) * 8) * HSTRIDE +
                                      ((lane >> 3) & 1) * 16);

    const int T = Kdim / BKH;

#pragma unroll
    for (int s = 0; s < 2; ++s) {
        const uint32_t sa = sbase + s * HSTAGE + sOff;
        const uint32_t sb = sa + HTILE;
        const __half* ga = gA + s * BKH;
        const __half* gb = gB + s * BKH;
#pragma unroll
        for (int i = 0; i < 4; ++i) {
            cp_async16(sa + i * 16, ga + i * 8);
            cp_async16(sb + i * 16, gb + i * 8);
        }
        cp_commit();
    }

    for (int t = 0; t < T; ++t) {
        if (t == T - 1) cp_wait<0>(); else cp_wait<1>();
        __syncthreads();
        if (t + 2 < T) {
            const int sidx = (t + 2) % NSTG;
            const uint32_t sa = sbase + sidx * HSTAGE + sOff;
            const uint32_t sb = sa + HTILE;
            const __half* ga = gA + (t + 2) * BKH;
            const __half* gb = gB + (t + 2) * BKH;
#pragma unroll
            for (int i = 0; i < 4; ++i) {
                cp_async16(sa + i * 16, ga + i * 8);
                cp_async16(sb + i * 16, gb + i * 8);
            }
            cp_commit();
        }
        const int buf = t % NSTG;
        const uint32_t abase = sbase + buf * HSTAGE + aoff0;
        const uint32_t bbase = sbase + buf * HSTAGE + HTILE + boff0;
#pragma unroll
        for (int ks = 0; ks < 4; ++ks) {
            uint32_t af[2][4];
            uint32_t bf[4][4];
#pragma unroll
            for (int mi = 0; mi < 2; ++mi)
                ldm_x4(af[mi], abase + mi * 16 * HSTRIDE + ks * 32);
#pragma unroll
            for (int nt = 0; nt < 4; ++nt)
                ldm_x4(bf[nt], bbase + nt * 16 * HSTRIDE + ks * 32);
#pragma unroll
            for (int mi = 0; mi < 2; ++mi)
#pragma unroll
                for (int ni = 0; ni < 8; ++ni)
                    mma_f16(acc[mi][ni], af[mi], &bf[ni >> 1][(ni & 1) * 2]);
        }
    }
    __syncthreads();

    // epilogue
    const int lr = lane >> 2, lc = lane & 3;
    const float* brow = bias + col0 + wn * 64;

    if (!SPLIT) {
#pragma unroll
        for (int mi = 0; mi < 2; ++mi) {
            const int mrow = row0 + wm * 32 + mi * 16 + lr;
#pragma unroll
            for (int hf = 0; hf < 2; ++hf) {
                float* Cr = Cf + (size_t)(mrow + hf * 8) * Ndim + col0 + wn * 64;
#pragma unroll
                for (int ni = 0; ni < 8; ++ni) {
                    float2 o;
                    o.x = acc[mi][ni][hf * 2 + 0] + brow[ni * 8 + 2 * lc];
                    o.y = acc[mi][ni][hf * 2 + 1] + brow[ni * 8 + 2 * lc + 1];
                    *(float2*)(Cr + ni * 8 + 2 * lc) = o;
                }
            }
        }
    } else if (col0 >= QK2) {
        // v mode: plain half
#pragma unroll
        for (int mi = 0; mi < 2; ++mi) {
            const int mrow = row0 + wm * 32 + mi * 16 + lr;
#pragma unroll
            for (int hf = 0; hf < 2; ++hf) {
                __half* Hr = g_vh + (size_t)(mrow + hf * 8) * CC + (col0 - QK2) + wn * 64;
#pragma unroll
                for (int ni = 0; ni < 8; ++ni) {
                    float ox = acc[mi][ni][hf * 2 + 0] + brow[ni * 8 + 2 * lc];
                    float oy = acc[mi][ni][hf * 2 + 1] + brow[ni * 8 + 2 * lc + 1];
                    *(__half2*)(Hr + ni * 8 + 2 * lc) = __floats2half2_rn(ox, oy);
                }
            }
        }
    } else {
        // q/k focus-t mode: t = (relu(val)+1e-6)/scale, write half + row partials
        const int seg = (col0 >= CC) ? 1 : 0;
        const int colbase = (col0 - seg * CC) + wn * 64;
        const int slot = ((col0 - seg * CC) >> 7) * 2 + wn;   // 0..15
        __half* Hbase = seg ? g_kh : g_qh;
        float2* fpart = seg ? g_fk : g_fq;
#pragma unroll
        for (int mi = 0; mi < 2; ++mi) {
#pragma unroll
            for (int hf = 0; hf < 2; ++hf) {
                const int r = row0 + wm * 32 + mi * 16 + lr + hf * 8;
                __half* Hr = Hbase + (size_t)r * CC + colbase;
                float s2 = 0.f, s6 = 0.f;
#pragma unroll
                for (int ni = 0; ni < 8; ++ni) {
                    const int c = colbase + ni * 8 + 2 * lc;
                    float2 sc = *(const float2*)(g_scale + c);
                    float vx = acc[mi][ni][hf * 2 + 0] + brow[ni * 8 + 2 * lc];
                    float vy = acc[mi][ni][hf * 2 + 1] + brow[ni * 8 + 2 * lc + 1];
                    float tx = (fmaxf(vx, 0.f) + 1e-6f) / sc.x;
                    float ty = (fmaxf(vy, 0.f) + 1e-6f) / sc.y;
                    float tx2 = tx * tx, ty2 = ty * ty;
                    s2 += tx2 + ty2;
                    s6 += tx2 * tx2 * tx2 + ty2 * ty2 * ty2;
                    *(__half2*)(Hr + ni * 8 + 2 * lc) = __floats2half2_rn(tx, ty);
                }
                s2 += __shfl_xor_sync(0xffffffffu, s2, 1);
                s6 += __shfl_xor_sync(0xffffffffu, s6, 1);
                s2 += __shfl_xor_sync(0xffffffffu, s2, 2);
                s6 += __shfl_xor_sync(0xffffffffu, s6, 2);
                if (lc == 0)
                    fpart[(size_t)r * 16 + slot] = make_float2(s2, s6);
            }
        }
    }
}

// ---------------------------------------------------------------------------
// Per-row focus factor: r = sqrt(sum t^2) * rsqrt(sum t^6)
// ---------------------------------------------------------------------------
__global__ void __launch_bounds__(256) focus_finalize_kernel() {
    const int idx = blockIdx.x * 256 + threadIdx.x;   // 0..2*MM-1
    const int seg = idx >> 14;                        // MM = 2^14
    const int r = idx & (MM - 1);
    const float2* fp = (seg ? g_fk : g_fq) + (size_t)r * 16;
    float S2 = 0.f, S6 = 0.f;
#pragma unroll
    for (int i = 0; i < 16; ++i) {
        float2 v = fp[i];
        S2 += v.x; S6 += v.y;
    }
    g_r[idx] = sqrtf(S2) * rsqrtf(S6);
}

// ---------------------------------------------------------------------------
// Per-head partial kv = u_K^T V and ksum(u_K) over a slice of N.
// u = t^3 * r_k[row] applied at smem fill.
// ---------------------------------------------------------------------------
__global__ void __launch_bounds__(256) kv_part_kernel() {
    const int bh = blockIdx.x;
    const int chunk = blockIdx.y;
    const int b = bh >> 4, h = bh & 15;
    __shared__ float Ks[64][68];
    __shared__ float Vs[64][68];
    __shared__ float kred[4][64];
    const int tid = threadIdx.x;
    const int tr = tid >> 4, tc = tid & 15;
    const int lr = tid >> 4;
    const int lc4 = (tid & 15) * 4;

    float acc[4][4];
#pragma unroll
    for (int i = 0; i < 4; ++i)
#pragma unroll
        for (int j = 0; j < 4; ++j) acc[i][j] = 0.f;
    float kpart = 0.f;
    const int scol = tid & 63, srg = tid >> 6;

    const int nlo = chunk * (NN / KVSPLIT);
    const int nhi = nlo + (NN / KVSPLIT);

    for (int n0 = nlo; n0 < nhi; n0 += 64) {
#pragma unroll
        for (int i = 0; i < 4; ++i) {
            const int r = lr + i * 16;
            const int grow = b * NN + n0 + r;
            const size_t off = (size_t)grow * CC + h * DD + lc4;
            const float rk = g_r[MM + grow];
            uint2 uk = *(const uint2*)(g_kh + off);
            uint2 uv = *(const uint2*)(g_vh + off);
            float2 k01 = __half22float2(*(__half2*)&uk.x);
            float2 k23 = __half22float2(*(__half2*)&uk.y);
            float2 v01 = __half22float2(*(__half2*)&uv.x);
            float2 v23 = __half22float2(*(__half2*)&uv.y);
            Ks[r][lc4 + 0] = k01.x * k01.x * k01.x * rk;
            Ks[r][lc4 + 1] = k01.y * k01.y * k01.y * rk;
            Ks[r][lc4 + 2] = k23.x * k23.x * k23.x * rk;
            Ks[r][lc4 + 3] = k23.y * k23.y * k23.y * rk;
            Vs[r][lc4 + 0] = v01.x; Vs[r][lc4 + 1] = v01.y;
            Vs[r][lc4 + 2] = v23.x; Vs[r][lc4 + 3] = v23.y;
        }
        __syncthreads();
#pragma unroll
        for (int kk = 0; kk < 64; ++kk) {
            float ra[4], rbv[4];
#pragma unroll
            for (int i = 0; i < 4; ++i) {
                ra[i] = Ks[kk][tr * 4 + i];
                rbv[i] = Vs[kk][tc * 4 + i];
            }
#pragma unroll
            for (int i = 0; i < 4; ++i)
#pragma unroll
                for (int j = 0; j < 4; ++j)
                    acc[i][j] = fmaf(ra[i], rbv[j], acc[i][j]);
        }
#pragma unroll
        for (int r = 0; r < 16; ++r) kpart += Ks[srg * 16 + r][scol];
        __syncthreads();
    }
    kred[srg][scol] = kpart;
    __syncthreads();
    const size_t pb = (size_t)(bh * KVSPLIT + chunk);
    if (tid < 64)
        g_ksp[pb * DD + tid] = kred[0][tid] + kred[1][tid] + kred[2][tid] + kred[3][tid];
#pragma unroll
    for (int i = 0; i < 4; ++i)
#pragma unroll
        for (int j = 0; j < 4; ++j)
            g_kvp[pb * 4096 + (tr * 4 + i) * 64 + tc * 4 + j] = acc[i][j];
}

__global__ void __launch_bounds__(256) kv_reduce_kernel() {
    const int bh = blockIdx.x;
    const int tid = threadIdx.x;
    for (int idx = tid; idx < 4096; idx += 256) {
        float s = 0.f;
#pragma unroll
        for (int c = 0; c < KVSPLIT; ++c)
            s += g_kvp[(size_t)(bh * KVSPLIT + c) * 4096 + idx];
        g_kv[(size_t)bh * 4096 + idx] = s;
    }
    if (tid < 64) {
        float s = 0.f;
#pragma unroll
        for (int c = 0; c < KVSPLIT; ++c)
            s += g_ksp[(size_t)(bh * KVSPLIT + c) * DD + tid];
        g_ksum[bh * DD + tid] = s;
    }
}

// ---------------------------------------------------------------------------
// Fused: o = (u_q @ kv) * z + depthwise-conv5(v) + dwc bias; u_q = t^3*r_q.
// ---------------------------------------------------------------------------
__global__ void __launch_bounds__(256) o_dwc_kernel(const float* __restrict__ w,
                                                    const float* __restrict__ bias) {
    const int bh = blockIdx.y;
    const int b = bh >> 4, h = bh & 15;
    const int n0 = blockIdx.x * 64;
    __shared__ float kvs[64][65];
    __shared__ float ks[64];
    __shared__ uint4 vsl4[68][8];
    const int tid = threadIdx.x;
    const int lane = tid & 31, warp = tid >> 5;

    for (int idx = tid; idx < 4096; idx += 256)
        kvs[idx >> 6][idx & 63] = g_kv[(size_t)bh * 4096 + idx];
    if (tid < 64) ks[tid] = g_ksum[bh * DD + tid];
    for (int idx = tid; idx < 68 * 8; idx += 256) {
        const int row = idx >> 3, seg = idx & 7;
        const int n = n0 - 2 + row;
        uint4 val = make_uint4(0u, 0u, 0u, 0u);
        if (n >= 0 && n < NN)
            val = *(const uint4*)(g_vh + (size_t)(b * NN + n) * CC + h * DD + seg * 8);
        vsl4[row][seg] = val;
    }
    __syncthreads();
    const __half* vs = (const __half*)vsl4;

    const int c1 = h * DD + lane, c2 = c1 + 32;
    float w1[5], w2[5];
#pragma unroll
    for (int j = 0; j < 5; ++j) { w1[j] = w[c1 * KER + j]; w2[j] = w[c2 * KER + j]; }
    const float b1 = bias[c1], b2 = bias[c2];

    for (int rr = 0; rr < 8; ++rr) {
        const int li = warp * 8 + rr;
        const int n = n0 + li;
        const size_t gr = (size_t)(b * NN + n);
        const float rq = g_r[gr];
        const __half* qrow = g_qh + gr * CC + h * DD;
        float ta = __half2float(qrow[lane]);
        float tb = __half2float(qrow[lane + 32]);
        float qa = ta * ta * ta * rq;
        float qb = tb * tb * tb * rq;
        float zp = qa * ks[lane] + qb * ks[lane + 32];
#pragma unroll
        for (int o = 16; o; o >>= 1) zp += __shfl_xor_sync(0xffffffffu, zp, o);
        float z = 1.0f / (zp + 1e-6f);
        float o1 = 0.f, o2 = 0.f;
#pragma unroll
        for (int d = 0; d < 32; ++d) {
            float qd = __shfl_sync(0xffffffffu, qa, d);
            o1 = fmaf(qd, kvs[d][lane], o1);
            o2 = fmaf(qd, kvs[d][lane + 32], o2);
        }
#pragma unroll
        for (int d = 0; d < 32; ++d) {
            float qd = __shfl_sync(0xffffffffu, qb, d);
            o1 = fmaf(qd, kvs[d + 32][lane], o1);
            o2 = fmaf(qd, kvs[d + 32][lane + 32], o2);
        }
        float d1 = b1, d2 = b2;
#pragma unroll
        for (int j = 0; j < 5; ++j) {
            d1 = fmaf(w1[j], __half2float(vs[(li + j) * 64 + lane]), d1);
            d2 = fmaf(w2[j], __half2float(vs[(li + j) * 64 + lane + 32]), d2);
        }
        __half* orow = g_oh + gr * CC + h * DD;
        orow[lane] = __float2half_rn(fmaf(o1, z, d1));
        orow[lane + 32] = __float2half_rn(fmaf(o2, z, d2));
    }
}

// ---------------------------------------------------------------------------
// Launch (ordered so the QKV GEMM is the 6th launch -> captured by ncu -s 5)
// ---------------------------------------------------------------------------
extern "C" void kernel_launch(void* const* d_in, const int* in_sizes, int n_in,
                              void* d_out, int out_size) {
    const float* x       = (const float*)d_in[0];
    const float* gamma   = (const float*)d_in[1];
    const float* beta    = (const float*)d_in[2];
    const float* Wqkv    = (const float*)d_in[3];
    const float* bqkv    = (const float*)d_in[4];
    const float* scale_p = (const float*)d_in[5];
    const float* dwc_w   = (const float*)d_in[6];
    const float* dwc_b   = (const float*)d_in[7];
    const float* Wproj   = (const float*)d_in[8];
    const float* bproj   = (const float*)d_in[9];
    float* out = (float*)d_out;

    __half* xh_ptr;  cudaGetSymbolAddress((void**)&xh_ptr, g_xh);
    __half* whq_ptr; cudaGetSymbolAddress((void**)&whq_ptr, g_whq);
    __half* whp_ptr; cudaGetSymbolAddress((void**)&whp_ptr, g_whp);
    __half* oh_ptr;  cudaGetSymbolAddress((void**)&oh_ptr, g_oh);
    float*  b2_ptr;  cudaGetSymbolAddress((void**)&b2_ptr, g_bias2);

    cudaFuncSetAttribute(gemm_hmma<true>,  cudaFuncAttributeMaxDynamicSharedMemorySize, GEMM_SMEM3);
    cudaFuncSetAttribute(gemm_hmma<false>, cudaFuncAttributeMaxDynamicSharedMemorySize, GEMM_SMEM3);

    // 1-2. BN statistics (fused with x -> half)
    bnf2h_kernel<<<256, 256>>>(x, xh_ptr);
    bn_finalize_kernel<<<4, 256>>>(gamma, beta, scale_p);

    // 3-5. Wqkv transpose (BN scale folded); shift -> bias (split-K)
    transpose_h_kernel<true><<<dim3(K3 / 32, CC / 32), 256>>>(Wqkv, whq_ptr, CC, K3);
    biasfold_part_kernel<<<dim3(K3 / 256, BFSPLIT), 256>>>(Wqkv);
    biasfold_reduce_kernel<<<K3 / 256, 256>>>(bqkv);

    // 6. QKV GEMM with fused focus-t epilogue (q,k -> t half + partials; v -> half)
    gemm_hmma<true><<<dim3(K3 / 128, MM / 128), 256, GEMM_SMEM3>>>(
        xh_ptr, whq_ptr, b2_ptr, (float*)nullptr, K3, CC);

    // 7. Per-row focus factors
    focus_finalize_kernel<<<2 * MM / 256, 256>>>();

    // 8. Wproj transpose (needed only before proj GEMM)
    transpose_h_kernel<false><<<dim3(CC / 32, CC / 32), 256>>>(Wproj, whp_ptr, CC, CC);

    // 9-10. Per-head kv = u_K^T V and ksum (split over N, then reduce)
    kv_part_kernel<<<dim3(BB * HH, KVSPLIT), 256>>>();
    kv_reduce_kernel<<<BB * HH, 256>>>();

    // 11. Fused attention output + depthwise conv -> half g_oh
    o_dwc_kernel<<<dim3(NN / 64, BB * HH), 256>>>(dwc_w, dwc_b);

    // 12. Projection GEMM (f32 out)
    gemm_hmma<false><<<dim3(CC / 128, MM / 128), 256, GEMM_SMEM3>>>(
        oh_ptr, whp_ptr, bproj, out, CC, CC);
}

// round 13
// speedup vs baseline: 1.2115x; 1.1256x over previous
#include <cuda_runtime.h>
#include <cuda_fp16.h>
#include <cstdint>

// Problem constants
#define BB 8
#define NN 2048
#define CC 1024
#define HH 16
#define DD 64
#define MM (BB * NN)        // 16384 rows
#define K3 (3 * CC)         // 3072
#define KER 5
#define QK2 (2 * CC)        // 2048

// GEMM tiling (fp16 mma.sync m16n8k16 + ldmatrix, 3-stage cp.async)
#define BKH 64                        // K halves per stage = 128 B/row
#define HSTRIDE 144                   // smem row stride bytes (72 halves, conflict-free)
#define HTILE (128 * HSTRIDE)         // 18432 per operand tile
#define HSTAGE (2 * HTILE)            // A + B = 36864
#define NSTG 3
#define GEMM_SMEM3 (NSTG * HSTAGE)    // 110592
#define GEMM_SMEM_TOT (GEMM_SMEM3 + 512)

#define KVSPLIT 8
#define BFSPLIT 16

// ---------------------------------------------------------------------------
// Scratch (device globals; no allocations allowed)
// ---------------------------------------------------------------------------
__device__ __half g_vh[(size_t)MM * CC];        // v half
__device__ __half g_qh[(size_t)MM * CC];        // q "t" half (pre-cube focus val)
__device__ __half g_kh[(size_t)MM * CC];        // k "t" half
__device__ __half g_oh[(size_t)MM * CC];        // attention+dwc (half, proj A operand)
__device__ __half g_xh[(size_t)MM * CC];        // x in half
__device__ __half g_whq[(size_t)K3 * CC];       // (a ⊙ W_qkv)^T half
__device__ __half g_whp[(size_t)CC * CC];       // W_proj^T half
__device__ float2 g_fq[(size_t)MM * 16];        // q row partials (sum t^2, sum t^6)
__device__ float2 g_fk[(size_t)MM * 16];        // k row partials
__device__ float  g_r[2 * MM];                  // per-row focus factor (q then k)
__device__ float  g_kv[BB * HH * DD * DD];
__device__ float  g_ksum[BB * HH * DD];
__device__ float  g_kvp[(size_t)BB * HH * KVSPLIT * DD * DD];
__device__ float  g_ksp[BB * HH * KVSPLIT * DD];
__device__ float  g_part[256 * 2 * CC];
__device__ float  g_bp[BFSPLIT * K3];
__device__ float  g_a[CC], g_shift[CC], g_scale[CC];

// ---------------------------------------------------------------------------
// PTX helpers
// ---------------------------------------------------------------------------
__device__ __forceinline__ uint32_t smem_u32(const void* p) {
    uint32_t a;
    asm("{ .reg .u64 t; cvta.to.shared.u64 t, %1; cvt.u32.u64 %0, t; }" : "=r"(a) : "l"(p));
    return a;
}
__device__ __forceinline__ void cp_async16(uint32_t saddr, const void* gptr) {
    asm volatile("cp.async.cg.shared.global [%0], [%1], 16;" :: "r"(saddr), "l"(gptr) : "memory");
}
__device__ __forceinline__ void cp_commit() {
    asm volatile("cp.async.commit_group;" ::: "memory");
}
template <int N>
__device__ __forceinline__ void cp_wait() {
    asm volatile("cp.async.wait_group %0;" :: "n"(N) : "memory");
}
__device__ __forceinline__ void ldm_x4(uint32_t* r, uint32_t addr) {
    asm volatile("ldmatrix.sync.aligned.m8n8.x4.shared.b16 {%0,%1,%2,%3}, [%4];"
                 : "=r"(r[0]), "=r"(r[1]), "=r"(r[2]), "=r"(r[3]) : "r"(addr));
}
__device__ __forceinline__ void mma_f16(float* c, const uint32_t* a, const uint32_t* b) {
    asm volatile(
        "mma.sync.aligned.m16n8k16.row.col.f32.f16.f16.f32 "
        "{%0,%1,%2,%3}, {%4,%5,%6,%7}, {%8,%9}, {%0,%1,%2,%3};"
        : "+f"(c[0]), "+f"(c[1]), "+f"(c[2]), "+f"(c[3])
        : "r"(a[0]), "r"(a[1]), "r"(a[2]), "r"(a[3]), "r"(b[0]), "r"(b[1]));
}
// Packed f32x2 (Blackwell): one instruction, two fp32 FMAs
__device__ __forceinline__ void ffma2(uint64_t& c, uint64_t a, uint64_t b) {
    asm("fma.rn.f32x2 %0, %1, %2, %0;" : "+l"(c) : "l"(a), "l"(b));
}
__device__ __forceinline__ uint64_t pack2(float lo, float hi) {
    uint64_t r;
    asm("mov.b64 %0, {%1, %2};" : "=l"(r) : "f"(lo), "f"(hi));
    return r;
}
__device__ __forceinline__ float2 unpack2(uint64_t v) {
    float2 r;
    asm("mov.b64 {%0, %1}, %2;" : "=f"(r.x), "=f"(r.y) : "l"(v));
    return r;
}

// ---------------------------------------------------------------------------
// BN stats partial sums fused with x -> half conversion.
// ---------------------------------------------------------------------------
__global__ void __launch_bounds__(256) bnf2h_kernel(const float* __restrict__ x,
                                                    __half* __restrict__ xh) {
    const int blk = blockIdx.x;
    const int tid = threadIdx.x;
    const int r0 = blk * 64;
    float s[4] = {0.f, 0.f, 0.f, 0.f};
    float ss[4] = {0.f, 0.f, 0.f, 0.f};
    for (int r = 0; r < 64; ++r) {
        const size_t rowo = (size_t)(r0 + r) * CC;
        float4 v = *(const float4*)(x + rowo + tid * 4);
        s[0] += v.x; ss[0] += v.x * v.x;
        s[1] += v.y; ss[1] += v.y * v.y;
        s[2] += v.z; ss[2] += v.z * v.z;
        s[3] += v.w; ss[3] += v.w * v.w;
        __half2 h0 = __floats2half2_rn(v.x, v.y);
        __half2 h1 = __floats2half2_rn(v.z, v.w);
        uint2 u;
        u.x = *(uint32_t*)&h0; u.y = *(uint32_t*)&h1;
        *(uint2*)(xh + rowo + tid * 4) = u;
    }
#pragma unroll
    for (int j = 0; j < 4; ++j) {
        g_part[(size_t)blk * 2048 + tid * 4 + j] = s[j];
        g_part[(size_t)blk * 2048 + 1024 + tid * 4 + j] = ss[j];
    }
}

__global__ void bn_finalize_kernel(const float* __restrict__ gamma,
                                   const float* __restrict__ beta,
                                   const float* __restrict__ scale_p) {
    const int ch = blockIdx.x * 256 + threadIdx.x;
    float s = 0.f, ss = 0.f;
    for (int b = 0; b < 256; ++b) {
        s += g_part[(size_t)b * 2048 + ch];
        ss += g_part[(size_t)b * 2048 + 1024 + ch];
    }
    const float inv = 1.0f / (float)MM;
    float mean = s * inv;
    float var = ss * inv - mean * mean;
    float rstd = rsqrtf(var + 1e-5f);
    float a = rstd * gamma[ch];
    g_a[ch] = a;
    g_shift[ch] = beta[ch] - mean * a;
    float p = scale_p[ch];
    g_scale[ch] = fmaxf(p, 0.f) + log1pf(expf(-fabsf(p)));
}

// ---------------------------------------------------------------------------
// Prep (fused): z=0 -> transpose Wqkv (K,N)->(N,K) half with g_a folded;
//               z=1 -> biasfold partials g_bp[c][n] = sum_{k in chunk} shift[k]*W[k][n]
// grid (96, 32, 2)
// ---------------------------------------------------------------------------
__global__ void __launch_bounds__(256) prep_kernel(const float* __restrict__ W) {
    __shared__ float t[32][33];
    if (blockIdx.z == 0) {
        const int n0 = blockIdx.x * 32, k0 = blockIdx.y * 32;
        const int tx = threadIdx.x & 31, ty = threadIdx.x >> 5;
#pragma unroll
        for (int i = 0; i < 4; ++i)
            t[ty + i * 8][tx] = W[(size_t)(k0 + ty + i * 8) * K3 + n0 + tx];
        __syncthreads();
        const float ak = g_a[k0 + tx];
#pragma unroll
        for (int i = 0; i < 4; ++i)
            g_whq[(size_t)(n0 + ty + i * 8) * CC + k0 + tx] =
                __float2half_rn(ak * t[tx][ty + i * 8]);
    } else {
        if (blockIdx.x < 12 && blockIdx.y < 16) {
            const int n = blockIdx.x * 256 + threadIdx.x;
            const int k0 = blockIdx.y * (CC / BFSPLIT);
            float s = 0.f;
#pragma unroll 8
            for (int k = 0; k < CC / BFSPLIT; ++k)
                s += g_shift[k0 + k] * W[(size_t)(k0 + k) * K3 + n];
            g_bp[(size_t)blockIdx.y * K3 + n] = s;
        }
    }
}

// ---------------------------------------------------------------------------
// Transpose W (K,N) -> Wt (N,K) half (no scale) — for Wproj.
// ---------------------------------------------------------------------------
__global__ void __launch_bounds__(256) transpose_h_kernel(
    const float* __restrict__ W, __half* __restrict__ Wt, int K, int N)
{
    __shared__ float t[32][33];
    const int n0 = blockIdx.x * 32, k0 = blockIdx.y * 32;
    const int tx = threadIdx.x & 31, ty = threadIdx.x >> 5;
#pragma unroll
    for (int i = 0; i < 4; ++i)
        t[ty + i * 8][tx] = W[(size_t)(k0 + ty + i * 8) * N + n0 + tx];
    __syncthreads();
#pragma unroll
    for (int i = 0; i < 4; ++i)
        Wt[(size_t)(n0 + ty + i * 8) * K + k0 + tx] = __float2half_rn(t[tx][ty + i * 8]);
}

// ---------------------------------------------------------------------------
// fp16 mma.sync GEMM. Block 128x128, BK=64, 8 warps (4m x 2n), warp 32x64,
// 3-stage cp.async.
// SPLIT (QKV): bias built in smem from bias[] + 16 g_bp partials.
//   cols < CC  -> focus-t half to g_qh + row partials g_fq
//   cols < QK2 -> focus-t half to g_kh + row partials g_fk
//   cols >= QK2-> plain half to g_vh
// !SPLIT (proj): f32 to Cf, bias read directly.
// ---------------------------------------------------------------------------
template <bool SPLIT>
__global__ void __launch_bounds__(256, 2) gemm_hmma(
    const __half* __restrict__ A, const __half* __restrict__ Bt,
    const float* __restrict__ bias, float* __restrict__ Cf,
    int Ndim, int Kdim)
{
    extern __shared__ char sm[];
    const int tid = threadIdx.x;
    const int lane = tid & 31, w = tid >> 5;
    const int wm = w & 3, wn = w >> 2;
    const int row0 = blockIdx.y * 128, col0 = blockIdx.x * 128;
    const uint32_t sbase = smem_u32(sm);
    float* sbias = (float*)(sm + GEMM_SMEM3);

    if (SPLIT && tid < 128) {
        const int c = col0 + tid;
        float s = bias[c];
#pragma unroll
        for (int i = 0; i < BFSPLIT; ++i) s += g_bp[(size_t)i * K3 + c];
        sbias[tid] = s;
    }

    const int lrow = tid >> 1, lh = tid & 1;
    const __half* gA = A + (size_t)(row0 + lrow) * Kdim + lh * 32;
    const __half* gB = Bt + (size_t)(col0 + lrow) * Kdim + lh * 32;
    const uint32_t sOff = (uint32_t)(lrow * HSTRIDE + lh * 64);

    float acc[2][8][4];
#pragma unroll
    for (int mi = 0; mi < 2; ++mi)
#pragma unroll
        for (int ni = 0; ni < 8; ++ni)
#pragma unroll
            for (int j = 0; j < 4; ++j) acc[mi][ni][j] = 0.f;

    const uint32_t aoff0 = (uint32_t)((wm * 32 + (lane & 15)) * HSTRIDE + (lane >> 4) * 16);
    const uint32_t boff0 = (uint32_t)((wn * 64 + (lane & 7) + (lane >> 4) * 8) * HSTRIDE +
                                      ((lane >> 3) & 1) * 16);

    const int T = Kdim / BKH;

#pragma unroll
    for (int s = 0; s < 2; ++s) {
        const uint32_t sa = sbase + s * HSTAGE + sOff;
        const uint32_t sb = sa + HTILE;
        const __half* ga = gA + s * BKH;
        const __half* gb = gB + s * BKH;
#pragma unroll
        for (int i = 0; i < 4; ++i) {
            cp_async16(sa + i * 16, ga + i * 8);
            cp_async16(sb + i * 16, gb + i * 8);
        }
        cp_commit();
    }

    for (int t = 0; t < T; ++t) {
        if (t == T - 1) cp_wait<0>(); else cp_wait<1>();
        __syncthreads();
        if (t + 2 < T) {
            const int sidx = (t + 2) % NSTG;
            const uint32_t sa = sbase + sidx * HSTAGE + sOff;
            const uint32_t sb = sa + HTILE;
            const __half* ga = gA + (t + 2) * BKH;
            const __half* gb = gB + (t + 2) * BKH;
#pragma unroll
            for (int i = 0; i < 4; ++i) {
                cp_async16(sa + i * 16, ga + i * 8);
                cp_async16(sb + i * 16, gb + i * 8);
            }
            cp_commit();
        }
        const int buf = t % NSTG;
        const uint32_t abase = sbase + buf * HSTAGE + aoff0;
        const uint32_t bbase = sbase + buf * HSTAGE + HTILE + boff0;
#pragma unroll
        for (int ks = 0; ks < 4; ++ks) {
            uint32_t af[2][4];
            uint32_t bf[4][4];
#pragma unroll
            for (int mi = 0; mi < 2; ++mi)
                ldm_x4(af[mi], abase + mi * 16 * HSTRIDE + ks * 32);
#pragma unroll
            for (int nt = 0; nt < 4; ++nt)
                ldm_x4(bf[nt], bbase + nt * 16 * HSTRIDE + ks * 32);
#pragma unroll
            for (int mi = 0; mi < 2; ++mi)
#pragma unroll
                for (int ni = 0; ni < 8; ++ni)
                    mma_f16(acc[mi][ni], af[mi], &bf[ni >> 1][(ni & 1) * 2]);
        }
    }
    __syncthreads();

    // epilogue
    const int lr = lane >> 2, lc = lane & 3;
    const float* brow = SPLIT ? (sbias + wn * 64) : (bias + col0 + wn * 64);

    if (!SPLIT) {
#pragma unroll
        for (int mi = 0; mi < 2; ++mi) {
            const int mrow = row0 + wm * 32 + mi * 16 + lr;
#pragma unroll
            for (int hf = 0; hf < 2; ++hf) {
                float* Cr = Cf + (size_t)(mrow + hf * 8) * Ndim + col0 + wn * 64;
#pragma unroll
                for (int ni = 0; ni < 8; ++ni) {
                    float2 o;
                    o.x = acc[mi][ni][hf * 2 + 0] + brow[ni * 8 + 2 * lc];
                    o.y = acc[mi][ni][hf * 2 + 1] + brow[ni * 8 + 2 * lc + 1];
                    *(float2*)(Cr + ni * 8 + 2 * lc) = o;
                }
            }
        }
    } else if (col0 >= QK2) {
        // v mode: plain half
#pragma unroll
        for (int mi = 0; mi < 2; ++mi) {
            const int mrow = row0 + wm * 32 + mi * 16 + lr;
#pragma unroll
            for (int hf = 0; hf < 2; ++hf) {
                __half* Hr = g_vh + (size_t)(mrow + hf * 8) * CC + (col0 - QK2) + wn * 64;
#pragma unroll
                for (int ni = 0; ni < 8; ++ni) {
                    float ox = acc[mi][ni][hf * 2 + 0] + brow[ni * 8 + 2 * lc];
                    float oy = acc[mi][ni][hf * 2 + 1] + brow[ni * 8 + 2 * lc + 1];
                    *(__half2*)(Hr + ni * 8 + 2 * lc) = __floats2half2_rn(ox, oy);
                }
            }
        }
    } else {
        // q/k focus-t mode
        const int seg = (col0 >= CC) ? 1 : 0;
        const int colbase = (col0 - seg * CC) + wn * 64;
        const int slot = ((col0 - seg * CC) >> 7) * 2 + wn;   // 0..15
        __half* Hbase = seg ? g_kh : g_qh;
        float2* fpart = seg ? g_fk : g_fq;
#pragma unroll
        for (int mi = 0; mi < 2; ++mi) {
#pragma unroll
            for (int hf = 0; hf < 2; ++hf) {
                const int r = row0 + wm * 32 + mi * 16 + lr + hf * 8;
                __half* Hr = Hbase + (size_t)r * CC + colbase;
                float s2 = 0.f, s6 = 0.f;
#pragma unroll
                for (int ni = 0; ni < 8; ++ni) {
                    const int c = colbase + ni * 8 + 2 * lc;
                    float2 sc = *(const float2*)(g_scale + c);
                    float vx = acc[mi][ni][hf * 2 + 0] + brow[ni * 8 + 2 * lc];
                    float vy = acc[mi][ni][hf * 2 + 1] + brow[ni * 8 + 2 * lc + 1];
                    float tx = (fmaxf(vx, 0.f) + 1e-6f) / sc.x;
                    float ty = (fmaxf(vy, 0.f) + 1e-6f) / sc.y;
                    float tx2 = tx * tx, ty2 = ty * ty;
                    s2 += tx2 + ty2;
                    s6 += tx2 * tx2 * tx2 + ty2 * ty2 * ty2;
                    *(__half2*)(Hr + ni * 8 + 2 * lc) = __floats2half2_rn(tx, ty);
                }
                s2 += __shfl_xor_sync(0xffffffffu, s2, 1);
                s6 += __shfl_xor_sync(0xffffffffu, s6, 1);
                s2 += __shfl_xor_sync(0xffffffffu, s2, 2);
                s6 += __shfl_xor_sync(0xffffffffu, s6, 2);
                if (lc == 0)
                    fpart[(size_t)r * 16 + slot] = make_float2(s2, s6);
            }
        }
    }
}

// ---------------------------------------------------------------------------
// Per-row focus factor: r = sqrt(sum t^2) * rsqrt(sum t^6)
// ---------------------------------------------------------------------------
__global__ void __launch_bounds__(256) focus_finalize_kernel() {
    const int idx = blockIdx.x * 256 + threadIdx.x;   // 0..2*MM-1
    const int seg = idx >> 14;                        // MM = 2^14
    const int r = idx & (MM - 1);
    const float2* fp = (seg ? g_fk : g_fq) + (size_t)r * 16;
    float S2 = 0.f, S6 = 0.f;
#pragma unroll
    for (int i = 0; i < 16; ++i) {
        float2 v = fp[i];
        S2 += v.x; S6 += v.y;
    }
    g_r[idx] = sqrtf(S2) * rsqrtf(S6);
}

// ---------------------------------------------------------------------------
// Per-head partial kv = u_K^T V and ksum(u_K) over a slice of N.
// u = t^3 * r_k[row] at smem fill; inner product via packed f32x2 FMA.
// ---------------------------------------------------------------------------
__global__ void __launch_bounds__(256) kv_part_kernel() {
    const int bh = blockIdx.x;
    const int chunk = blockIdx.y;
    const int b = bh >> 4, h = bh & 15;
    __shared__ float Ks[64][68];
    __shared__ float Vs[64][68];
    __shared__ float kred[4][64];
    const int tid = threadIdx.x;
    const int tr = tid >> 4, tc = tid & 15;
    const int lr = tid >> 4;
    const int lc4 = (tid & 15) * 4;

    uint64_t acc2[4][2];
#pragma unroll
    for (int i = 0; i < 4; ++i) { acc2[i][0] = 0ull; acc2[i][1] = 0ull; }
    float kpart = 0.f;
    const int scol = tid & 63, srg = tid >> 6;

    const int nlo = chunk * (NN / KVSPLIT);
    const int nhi = nlo + (NN / KVSPLIT);

    for (int n0 = nlo; n0 < nhi; n0 += 64) {
#pragma unroll
        for (int i = 0; i < 4; ++i) {
            const int r = lr + i * 16;
            const int grow = b * NN + n0 + r;
            const size_t off = (size_t)grow * CC + h * DD + lc4;
            const float rk = g_r[MM + grow];
            uint2 uk = *(const uint2*)(g_kh + off);
            uint2 uv = *(const uint2*)(g_vh + off);
            float2 k01 = __half22float2(*(__half2*)&uk.x);
            float2 k23 = __half22float2(*(__half2*)&uk.y);
            float2 v01 = __half22float2(*(__half2*)&uv.x);
            float2 v23 = __half22float2(*(__half2*)&uv.y);
            Ks[r][lc4 + 0] = k01.x * k01.x * k01.x * rk;
            Ks[r][lc4 + 1] = k01.y * k01.y * k01.y * rk;
            Ks[r][lc4 + 2] = k23.x * k23.x * k23.x * rk;
            Ks[r][lc4 + 3] = k23.y * k23.y * k23.y * rk;
            Vs[r][lc4 + 0] = v01.x; Vs[r][lc4 + 1] = v01.y;
            Vs[r][lc4 + 2] = v23.x; Vs[r][lc4 + 3] = v23.y;
        }
        __syncthreads();
#pragma unroll
        for (int kk = 0; kk < 64; ++kk) {
            float2 a01 = *(const float2*)&Ks[kk][tr * 4];
            float2 a23 = *(const float2*)&Ks[kk][tr * 4 + 2];
            float2 b01 = *(const float2*)&Vs[kk][tc * 4];
            float2 b23 = *(const float2*)&Vs[kk][tc * 4 + 2];
            const uint64_t bv0 = pack2(b01.x, b01.y);
            const uint64_t bv1 = pack2(b23.x, b23.y);
            const uint64_t a0 = pack2(a01.x, a01.x);
            const uint64_t a1 = pack2(a01.y, a01.y);
            const uint64_t a2 = pack2(a23.x, a23.x);
            const uint64_t a3 = pack2(a23.y, a23.y);
            ffma2(acc2[0][0], a0, bv0); ffma2(acc2[0][1], a0, bv1);
            ffma2(acc2[1][0], a1, bv0); ffma2(acc2[1][1], a1, bv1);
            ffma2(acc2[2][0], a2, bv0); ffma2(acc2[2][1], a2, bv1);
            ffma2(acc2[3][0], a3, bv0); ffma2(acc2[3][1], a3, bv1);
        }
#pragma unroll
        for (int r = 0; r < 16; ++r) kpart += Ks[srg * 16 + r][scol];
        __syncthreads();
    }
    kred[srg][scol] = kpart;
    __syncthreads();
    const size_t pb = (size_t)(bh * KVSPLIT + chunk);
    if (tid < 64)
        g_ksp[pb * DD + tid] = kred[0][tid] + kred[1][tid] + kred[2][tid] + kred[3][tid];
#pragma unroll
    for (int i = 0; i < 4; ++i) {
#pragma unroll
        for (int jp = 0; jp < 2; ++jp) {
            float2 u = unpack2(acc2[i][jp]);
            g_kvp[pb * 4096 + (tr * 4 + i) * 64 + tc * 4 + jp * 2 + 0] = u.x;
            g_kvp[pb * 4096 + (tr * 4 + i) * 64 + tc * 4 + jp * 2 + 1] = u.y;
        }
    }
}

__global__ void __launch_bounds__(256) kv_reduce_kernel() {
    const int bh = blockIdx.x;
    const int tid = threadIdx.x;
    for (int idx = tid; idx < 4096; idx += 256) {
        float s = 0.f;
#pragma unroll
        for (int c = 0; c < KVSPLIT; ++c)
            s += g_kvp[(size_t)(bh * KVSPLIT + c) * 4096 + idx];
        g_kv[(size_t)bh * 4096 + idx] = s;
    }
    if (tid < 64) {
        float s = 0.f;
#pragma unroll
        for (int c = 0; c < KVSPLIT; ++c)
            s += g_ksp[(size_t)(bh * KVSPLIT + c) * DD + tid];
        g_ksum[bh * DD + tid] = s;
    }
}

// ---------------------------------------------------------------------------
// Fused: o = (u_q @ kv) * z + depthwise-conv5(v) + dwc bias; writes half g_oh.
// u_q = t^3 * r_q materialized into smem once; inner loops use f32x2 FMA,
// two rows per step, thread covers column pair (2*lane, 2*lane+1).
// ---------------------------------------------------------------------------
__global__ void __launch_bounds__(256) o_dwc_kernel(const float* __restrict__ w,
                                                    const float* __restrict__ bias) {
    const int bh = blockIdx.y;
    const int b = bh >> 4, h = bh & 15;
    const int n0 = blockIdx.x * 64;
    __shared__ float qs[64][66];       // u_q tile
    __shared__ float2 kvf2[64][32];    // kv as column pairs
    __shared__ uint4 vsl4[68][8];      // v slice [n0-2, n0+66) x 64 ch (half)
    __shared__ float ks[64];
    const int tid = threadIdx.x;
    const int lane = tid & 31, warp = tid >> 5;

    for (int idx = tid; idx < 1024; idx += 256)
        ((uint4*)kvf2)[idx] = ((const uint4*)(g_kv + (size_t)bh * 4096))[idx];
    if (tid < 64) ks[tid] = g_ksum[bh * DD + tid];
    for (int idx = tid; idx < 68 * 8; idx += 256) {
        const int row = idx >> 3, seg = idx & 7;
        const int n = n0 - 2 + row;
        uint4 val = make_uint4(0u, 0u, 0u, 0u);
        if (n >= 0 && n < NN)
            val = *(const uint4*)(g_vh + (size_t)(b * NN + n) * CC + h * DD + seg * 8);
        vsl4[row][seg] = val;
    }
    for (int idx = tid; idx < 2048; idx += 256) {
        const int row = idx >> 5, c = idx & 31;
        const int gr = b * NN + n0 + row;
        const float rq = g_r[gr];
        __half2 hv = *(const __half2*)(g_qh + (size_t)gr * CC + h * DD + 2 * c);
        float2 t = __half22float2(hv);
        qs[row][2 * c + 0] = t.x * t.x * t.x * rq;
        qs[row][2 * c + 1] = t.y * t.y * t.y * rq;
    }
    __syncthreads();

    const __half* vsh = (const __half*)vsl4;   // [68][64]
    const int c0 = h * DD + 2 * lane;          // column pair base
    uint64_t wp[5];
#pragma unroll
    for (int j = 0; j < 5; ++j)
        wp[j] = pack2(w[c0 * KER + j], w[(c0 + 1) * KER + j]);
    const uint64_t bp = pack2(bias[c0], bias[c0 + 1]);
    const float2 ks2 = *(const float2*)&ks[2 * lane];

    for (int rr = 0; rr < 4; ++rr) {
        const int li0 = warp * 8 + rr * 2, li1 = li0 + 1;
        // z for both rows (lane-parallel partial + shfl reduce)
        float2 q0p = *(const float2*)&qs[li0][2 * lane];
        float2 q1p = *(const float2*)&qs[li1][2 * lane];
        float zp0 = q0p.x * ks2.x + q0p.y * ks2.y;
        float zp1 = q1p.x * ks2.x + q1p.y * ks2.y;
#pragma unroll
        for (int o = 16; o; o >>= 1) {
            zp0 += __shfl_xor_sync(0xffffffffu, zp0, o);
            zp1 += __shfl_xor_sync(0xffffffffu, zp1, o);
        }
        const float z0 = 1.0f / (zp0 + 1e-6f);
        const float z1 = 1.0f / (zp1 + 1e-6f);

        uint64_t acc0 = 0ull, acc1 = 0ull;
#pragma unroll 16
        for (int d = 0; d < 64; ++d) {
            const float a0 = qs[li0][d];
            const float a1 = qs[li1][d];
            float2 kv = kvf2[d][lane];
            const uint64_t kvu = pack2(kv.x, kv.y);
            ffma2(acc0, pack2(a0, a0), kvu);
            ffma2(acc1, pack2(a1, a1), kvu);
        }

        uint64_t d0 = bp, d1 = bp;
#pragma unroll
        for (int j = 0; j < 5; ++j) {
            float2 v0 = __half22float2(*(const __half2*)(vsh + (li0 + j) * 64 + 2 * lane));
            float2 v1 = __half22float2(*(const __half2*)(vsh + (li1 + j) * 64 + 2 * lane));
            ffma2(d0, wp[j], pack2(v0.x, v0.y));
            ffma2(d1, wp[j], pack2(v1.x, v1.y));
        }

        float2 A0 = unpack2(acc0), A1 = unpack2(acc1);
        float2 D0 = unpack2(d0), D1 = unpack2(d1);
        __half* o0 = g_oh + (size_t)(b * NN + n0 + li0) * CC + c0;
        __half* o1 = g_oh + (size_t)(b * NN + n0 + li1) * CC + c0;
        *(__half2*)o0 = __floats2half2_rn(fmaf(A0.x, z0, D0.x), fmaf(A0.y, z0, D0.y));
        *(__half2*)o1 = __floats2half2_rn(fmaf(A1.x, z1, D1.x), fmaf(A1.y, z1, D1.y));
    }
}

// ---------------------------------------------------------------------------
// Launch (QKV GEMM is the 4th launch -> ncu capture slot)
// ---------------------------------------------------------------------------
extern "C" void kernel_launch(void* const* d_in, const int* in_sizes, int n_in,
                              void* d_out, int out_size) {
    const float* x       = (const float*)d_in[0];
    const float* gamma   = (const float*)d_in[1];
    const float* beta    = (const float*)d_in[2];
    const float* Wqkv    = (const float*)d_in[3];
    const float* bqkv    = (const float*)d_in[4];
    const float* scale_p = (const float*)d_in[5];
    const float* dwc_w   = (const float*)d_in[6];
    const float* dwc_b   = (const float*)d_in[7];
    const float* Wproj   = (const float*)d_in[8];
    const float* bproj   = (const float*)d_in[9];
    float* out = (float*)d_out;

    __half* xh_ptr;  cudaGetSymbolAddress((void**)&xh_ptr, g_xh);
    __half* whq_ptr; cudaGetSymbolAddress((void**)&whq_ptr, g_whq);
    __half* whp_ptr; cudaGetSymbolAddress((void**)&whp_ptr, g_whp);
    __half* oh_ptr;  cudaGetSymbolAddress((void**)&oh_ptr, g_oh);

    cudaFuncSetAttribute(gemm_hmma<true>,  cudaFuncAttributeMaxDynamicSharedMemorySize, GEMM_SMEM_TOT);
    cudaFuncSetAttribute(gemm_hmma<false>, cudaFuncAttributeMaxDynamicSharedMemorySize, GEMM_SMEM_TOT);

    // 1-2. BN statistics (fused with x -> half)
    bnf2h_kernel<<<256, 256>>>(x, xh_ptr);
    bn_finalize_kernel<<<4, 256>>>(gamma, beta, scale_p);

    // 3. Fused prep: Wqkv transpose (BN scale folded) + bias partials
    prep_kernel<<<dim3(96, 32, 2), 256>>>(Wqkv);

    // 4. QKV GEMM (fused focus-t epilogue; bias2 built in smem from partials)
    gemm_hmma<true><<<dim3(K3 / 128, MM / 128), 256, GEMM_SMEM_TOT>>>(
        xh_ptr, whq_ptr, bqkv, (float*)nullptr, K3, CC);

    // 5. Per-row focus factors
    focus_finalize_kernel<<<2 * MM / 256, 256>>>();

    // 6. Wproj transpose
    transpose_h_kernel<<<dim3(CC / 32, CC / 32), 256>>>(Wproj, whp_ptr, CC, CC);

    // 7-8. Per-head kv = u_K^T V and ksum (split over N, then reduce)
    kv_part_kernel<<<dim3(BB * HH, KVSPLIT), 256>>>();
    kv_reduce_kernel<<<BB * HH, 256>>>();

    // 9. Fused attention output + depthwise conv -> half g_oh
    o_dwc_kernel<<<dim3(NN / 64, BB * HH), 256>>>(dwc_w, dwc_b);

    // 10. Projection GEMM (f32 out)
    gemm_hmma<false><<<dim3(CC / 128, MM / 128), 256, GEMM_SMEM_TOT>>>(
        oh_ptr, whp_ptr, bproj, out, CC, CC);
}

// round 14
// speedup vs baseline: 1.2773x; 1.0543x over previous
#include <cuda_runtime.h>
#include <cuda_fp16.h>
#include <cstdint>

// Problem constants
#define BB 8
#define NN 2048
#define CC 1024
#define HH 16
#define DD 64
#define MM (BB * NN)        // 16384 rows
#define K3 (3 * CC)         // 3072
#define KER 5
#define QK2 (2 * CC)        // 2048

// GEMM tiling: fp16 mma.sync m16n8k16 + ldmatrix, BK=32, 5-stage cp.async ring
#define BKH 32                        // K halves per stage = 64 B/row
#define SSTRIDE 80                    // smem row stride bytes (64 + 16 pad, conflict-free)
#define HTILE (128 * SSTRIDE)         // 10240 per operand tile
#define HSTAGE (2 * HTILE)            // A + B = 20480
#define NSTG 5
#define GEMM_SMEM5 (NSTG * HSTAGE)    // 102400
#define GEMM_SMEM_TOT (GEMM_SMEM5 + 512)

#define KVSPLIT 8
#define BFSPLIT 16

// ---------------------------------------------------------------------------
// Scratch (device globals; no allocations allowed)
// ---------------------------------------------------------------------------
__device__ __half g_vh[(size_t)MM * CC];        // v half
__device__ __half g_qh[(size_t)MM * CC];        // q t^3 half (focus, pre-normalization)
__device__ __half g_kh[(size_t)MM * CC];        // k t^3 half
__device__ __half g_oh[(size_t)MM * CC];        // attention+dwc (half, proj A operand)
__device__ __half g_xh[(size_t)MM * CC];        // x in half
__device__ __half g_whq[(size_t)K3 * CC];       // (a ⊙ W_qkv)^T half
__device__ __half g_whp[(size_t)CC * CC];       // W_proj^T half
__device__ float2 g_fq[(size_t)MM * 16];        // q row partials (sum t^2, sum t^6)
__device__ float2 g_fk[(size_t)MM * 16];        // k row partials
__device__ float  g_r[2 * MM];                  // per-row focus factor (q then k)
__device__ float  g_kv[BB * HH * DD * DD];
__device__ float  g_ksum[BB * HH * DD];
__device__ float  g_kvp[(size_t)BB * HH * KVSPLIT * DD * DD];
__device__ float  g_ksp[BB * HH * KVSPLIT * DD];
__device__ float  g_part[256 * 2 * CC];
__device__ float  g_bp[BFSPLIT * K3];
__device__ float  g_a[CC], g_shift[CC], g_scale[CC];

// ---------------------------------------------------------------------------
// PTX helpers
// ---------------------------------------------------------------------------
__device__ __forceinline__ uint32_t smem_u32(const void* p) {
    uint32_t a;
    asm("{ .reg .u64 t; cvta.to.shared.u64 t, %1; cvt.u32.u64 %0, t; }" : "=r"(a) : "l"(p));
    return a;
}
__device__ __forceinline__ void cp_async16(uint32_t saddr, const void* gptr) {
    asm volatile("cp.async.cg.shared.global [%0], [%1], 16;" :: "r"(saddr), "l"(gptr) : "memory");
}
__device__ __forceinline__ void cp_commit() {
    asm volatile("cp.async.commit_group;" ::: "memory");
}
template <int N>
__device__ __forceinline__ void cp_wait() {
    asm volatile("cp.async.wait_group %0;" :: "n"(N) : "memory");
}
__device__ __forceinline__ void ldm_x4(uint32_t* r, uint32_t addr) {
    asm volatile("ldmatrix.sync.aligned.m8n8.x4.shared.b16 {%0,%1,%2,%3}, [%4];"
                 : "=r"(r[0]), "=r"(r[1]), "=r"(r[2]), "=r"(r[3]) : "r"(addr));
}
__device__ __forceinline__ void mma_f16(float* c, const uint32_t* a, const uint32_t* b) {
    asm volatile(
        "mma.sync.aligned.m16n8k16.row.col.f32.f16.f16.f32 "
        "{%0,%1,%2,%3}, {%4,%5,%6,%7}, {%8,%9}, {%0,%1,%2,%3};"
        : "+f"(c[0]), "+f"(c[1]), "+f"(c[2]), "+f"(c[3])
        : "r"(a[0]), "r"(a[1]), "r"(a[2]), "r"(a[3]), "r"(b[0]), "r"(b[1]));
}
// Packed f32x2 (Blackwell): one instruction, two fp32 FMAs
__device__ __forceinline__ void ffma2(uint64_t& c, uint64_t a, uint64_t b) {
    asm("fma.rn.f32x2 %0, %1, %2, %0;" : "+l"(c) : "l"(a), "l"(b));
}
__device__ __forceinline__ uint64_t pack2(float lo, float hi) {
    uint64_t r;
    asm("mov.b64 %0, {%1, %2};" : "=l"(r) : "f"(lo), "f"(hi));
    return r;
}
__device__ __forceinline__ float2 unpack2(uint64_t v) {
    float2 r;
    asm("mov.b64 {%0, %1}, %2;" : "=f"(r.x), "=f"(r.y) : "l"(v));
    return r;
}

// ---------------------------------------------------------------------------
// BN stats partial sums fused with x -> half conversion.
// ---------------------------------------------------------------------------
__global__ void __launch_bounds__(256) bnf2h_kernel(const float* __restrict__ x,
                                                    __half* __restrict__ xh) {
    const int blk = blockIdx.x;
    const int tid = threadIdx.x;
    const int r0 = blk * 64;
    float s[4] = {0.f, 0.f, 0.f, 0.f};
    float ss[4] = {0.f, 0.f, 0.f, 0.f};
    for (int r = 0; r < 64; ++r) {
        const size_t rowo = (size_t)(r0 + r) * CC;
        float4 v = *(const float4*)(x + rowo + tid * 4);
        s[0] += v.x; ss[0] += v.x * v.x;
        s[1] += v.y; ss[1] += v.y * v.y;
        s[2] += v.z; ss[2] += v.z * v.z;
        s[3] += v.w; ss[3] += v.w * v.w;
        __half2 h0 = __floats2half2_rn(v.x, v.y);
        __half2 h1 = __floats2half2_rn(v.z, v.w);
        uint2 u;
        u.x = *(uint32_t*)&h0; u.y = *(uint32_t*)&h1;
        *(uint2*)(xh + rowo + tid * 4) = u;
    }
#pragma unroll
    for (int j = 0; j < 4; ++j) {
        g_part[(size_t)blk * 2048 + tid * 4 + j] = s[j];
        g_part[(size_t)blk * 2048 + 1024 + tid * 4 + j] = ss[j];
    }
}

__global__ void bn_finalize_kernel(const float* __restrict__ gamma,
                                   const float* __restrict__ beta,
                                   const float* __restrict__ scale_p) {
    const int ch = blockIdx.x * 256 + threadIdx.x;
    float s = 0.f, ss = 0.f;
    for (int b = 0; b < 256; ++b) {
        s += g_part[(size_t)b * 2048 + ch];
        ss += g_part[(size_t)b * 2048 + 1024 + ch];
    }
    const float inv = 1.0f / (float)MM;
    float mean = s * inv;
    float var = ss * inv - mean * mean;
    float rstd = rsqrtf(var + 1e-5f);
    float a = rstd * gamma[ch];
    g_a[ch] = a;
    g_shift[ch] = beta[ch] - mean * a;
    float p = scale_p[ch];
    g_scale[ch] = fmaxf(p, 0.f) + log1pf(expf(-fabsf(p)));
}

// ---------------------------------------------------------------------------
// Prep (fused): z=0 -> transpose Wqkv (K,N)->(N,K) half with g_a folded;
//               z=1 -> biasfold partials
// ---------------------------------------------------------------------------
__global__ void __launch_bounds__(256) prep_kernel(const float* __restrict__ W) {
    __shared__ float t[32][33];
    if (blockIdx.z == 0) {
        const int n0 = blockIdx.x * 32, k0 = blockIdx.y * 32;
        const int tx = threadIdx.x & 31, ty = threadIdx.x >> 5;
#pragma unroll
        for (int i = 0; i < 4; ++i)
            t[ty + i * 8][tx] = W[(size_t)(k0 + ty + i * 8) * K3 + n0 + tx];
        __syncthreads();
        const float ak = g_a[k0 + tx];
#pragma unroll
        for (int i = 0; i < 4; ++i)
            g_whq[(size_t)(n0 + ty + i * 8) * CC + k0 + tx] =
                __float2half_rn(ak * t[tx][ty + i * 8]);
    } else {
        if (blockIdx.x < 12 && blockIdx.y < 16) {
            const int n = blockIdx.x * 256 + threadIdx.x;
            const int k0 = blockIdx.y * (CC / BFSPLIT);
            float s = 0.f;
#pragma unroll 8
            for (int k = 0; k < CC / BFSPLIT; ++k)
                s += g_shift[k0 + k] * W[(size_t)(k0 + k) * K3 + n];
            g_bp[(size_t)blockIdx.y * K3 + n] = s;
        }
    }
}

// ---------------------------------------------------------------------------
// Transpose W (K,N) -> Wt (N,K) half (no scale) — for Wproj.
// ---------------------------------------------------------------------------
__global__ void __launch_bounds__(256) transpose_h_kernel(
    const float* __restrict__ W, __half* __restrict__ Wt, int K, int N)
{
    __shared__ float t[32][33];
    const int n0 = blockIdx.x * 32, k0 = blockIdx.y * 32;
    const int tx = threadIdx.x & 31, ty = threadIdx.x >> 5;
#pragma unroll
    for (int i = 0; i < 4; ++i)
        t[ty + i * 8][tx] = W[(size_t)(k0 + ty + i * 8) * N + n0 + tx];
    __syncthreads();
#pragma unroll
    for (int i = 0; i < 4; ++i)
        Wt[(size_t)(n0 + ty + i * 8) * K + k0 + tx] = __float2half_rn(t[tx][ty + i * 8]);
}

// ---------------------------------------------------------------------------
// fp16 mma.sync GEMM. Block 128x128, BK=32, 8 warps (4m x 2n), warp 32x64,
// 5-stage cp.async ring (prefetch distance 4), single barrier per stage.
// SPLIT (QKV): bias built in smem from bias[] + 16 g_bp partials.
//   cols < CC  -> focus t^3 half to g_qh + row partials g_fq
//   cols < QK2 -> focus t^3 half to g_kh + row partials g_fk
//   cols >= QK2-> plain half to g_vh
// !SPLIT (proj): f32 to Cf, bias read directly.
// ---------------------------------------------------------------------------
template <bool SPLIT>
__global__ void __launch_bounds__(256, 2) gemm_hmma(
    const __half* __restrict__ A, const __half* __restrict__ Bt,
    const float* __restrict__ bias, float* __restrict__ Cf,
    int Ndim, int Kdim)
{
    extern __shared__ char sm[];
    const int tid = threadIdx.x;
    const int lane = tid & 31, w = tid >> 5;
    const int wm = w & 3, wn = w >> 2;
    const int row0 = blockIdx.y * 128, col0 = blockIdx.x * 128;
    const uint32_t sbase = smem_u32(sm);
    float* sbias = (float*)(sm + GEMM_SMEM5);

    if (SPLIT && tid < 128) {
        const int c = col0 + tid;
        float s = bias[c];
#pragma unroll
        for (int i = 0; i < BFSPLIT; ++i) s += g_bp[(size_t)i * K3 + c];
        sbias[tid] = s;
    }

    // loader: thread -> row tid>>1, 32B half (tid&1): two 16B chunks
    const int lrow = tid >> 1, lh = tid & 1;
    const __half* gA = A + (size_t)(row0 + lrow) * Kdim + lh * 16;
    const __half* gB = Bt + (size_t)(col0 + lrow) * Kdim + lh * 16;
    const uint32_t sOff = (uint32_t)(lrow * SSTRIDE + lh * 32);

    float acc[2][8][4];
#pragma unroll
    for (int mi = 0; mi < 2; ++mi)
#pragma unroll
        for (int ni = 0; ni < 8; ++ni)
#pragma unroll
            for (int j = 0; j < 4; ++j) acc[mi][ni][j] = 0.f;

    const uint32_t aoff0 = (uint32_t)((wm * 32 + (lane & 15)) * SSTRIDE + (lane >> 4) * 16);
    const uint32_t boff0 = (uint32_t)((wn * 64 + (lane & 7) + (lane >> 4) * 8) * SSTRIDE +
                                      ((lane >> 3) & 1) * 16);

    const int T = Kdim / BKH;

    // prologue: stages 0..3
#pragma unroll
    for (int s = 0; s < 4; ++s) {
        const uint32_t sa = sbase + s * HSTAGE + sOff;
        const uint32_t sb = sa + HTILE;
        const __half* ga = gA + s * BKH;
        const __half* gb = gB + s * BKH;
        cp_async16(sa, ga);
        cp_async16(sa + 16, ga + 8);
        cp_async16(sb, gb);
        cp_async16(sb + 16, gb + 8);
        cp_commit();
    }

    for (int t = 0; t < T; ++t) {
        if (t <= T - 4)      cp_wait<3>();
        else if (t == T - 3) cp_wait<2>();
        else if (t == T - 2) cp_wait<1>();
        else                 cp_wait<0>();
        __syncthreads();
        if (t + 4 < T) {
            const int sidx = (t + 4) % NSTG;
            const uint32_t sa = sbase + sidx * HSTAGE + sOff;
            const uint32_t sb = sa + HTILE;
            const __half* ga = gA + (t + 4) * BKH;
            const __half* gb = gB + (t + 4) * BKH;
            cp_async16(sa, ga);
            cp_async16(sa + 16, ga + 8);
            cp_async16(sb, gb);
            cp_async16(sb + 16, gb + 8);
            cp_commit();
        }
        const int buf = t % NSTG;
        const uint32_t abase = sbase + buf * HSTAGE + aoff0;
        const uint32_t bbase = sbase + buf * HSTAGE + HTILE + boff0;
#pragma unroll
        for (int ks = 0; ks < 2; ++ks) {
            uint32_t af[2][4];
            uint32_t bf[4][4];
#pragma unroll
            for (int mi = 0; mi < 2; ++mi)
                ldm_x4(af[mi], abase + mi * 16 * SSTRIDE + ks * 32);
#pragma unroll
            for (int nt = 0; nt < 4; ++nt)
                ldm_x4(bf[nt], bbase + nt * 16 * SSTRIDE + ks * 32);
#pragma unroll
            for (int mi = 0; mi < 2; ++mi)
#pragma unroll
                for (int ni = 0; ni < 8; ++ni)
                    mma_f16(acc[mi][ni], af[mi], &bf[ni >> 1][(ni & 1) * 2]);
        }
    }
    __syncthreads();

    // epilogue
    const int lr = lane >> 2, lc = lane & 3;
    const float* brow = SPLIT ? (sbias + wn * 64) : (bias + col0 + wn * 64);

    if (!SPLIT) {
#pragma unroll
        for (int mi = 0; mi < 2; ++mi) {
            const int mrow = row0 + wm * 32 + mi * 16 + lr;
#pragma unroll
            for (int hf = 0; hf < 2; ++hf) {
                float* Cr = Cf + (size_t)(mrow + hf * 8) * Ndim + col0 + wn * 64;
#pragma unroll
                for (int ni = 0; ni < 8; ++ni) {
                    float2 o;
                    o.x = acc[mi][ni][hf * 2 + 0] + brow[ni * 8 + 2 * lc];
                    o.y = acc[mi][ni][hf * 2 + 1] + brow[ni * 8 + 2 * lc + 1];
                    *(float2*)(Cr + ni * 8 + 2 * lc) = o;
                }
            }
        }
    } else if (col0 >= QK2) {
        // v mode: plain half
#pragma unroll
        for (int mi = 0; mi < 2; ++mi) {
            const int mrow = row0 + wm * 32 + mi * 16 + lr;
#pragma unroll
            for (int hf = 0; hf < 2; ++hf) {
                __half* Hr = g_vh + (size_t)(mrow + hf * 8) * CC + (col0 - QK2) + wn * 64;
#pragma unroll
                for (int ni = 0; ni < 8; ++ni) {
                    float ox = acc[mi][ni][hf * 2 + 0] + brow[ni * 8 + 2 * lc];
                    float oy = acc[mi][ni][hf * 2 + 1] + brow[ni * 8 + 2 * lc + 1];
                    *(__half2*)(Hr + ni * 8 + 2 * lc) = __floats2half2_rn(ox, oy);
                }
            }
        }
    } else {
        // q/k focus mode: t = (relu(val)+1e-6)/scale; store t^3 as half + partials
        const int seg = (col0 >= CC) ? 1 : 0;
        const int colbase = (col0 - seg * CC) + wn * 64;
        const int slot = ((col0 - seg * CC) >> 7) * 2 + wn;   // 0..15
        __half* Hbase = seg ? g_kh : g_qh;
        float2* fpart = seg ? g_fk : g_fq;
#pragma unroll
        for (int mi = 0; mi < 2; ++mi) {
#pragma unroll
            for (int hf = 0; hf < 2; ++hf) {
                const int r = row0 + wm * 32 + mi * 16 + lr + hf * 8;
                __half* Hr = Hbase + (size_t)r * CC + colbase;
                float s2 = 0.f, s6 = 0.f;
#pragma unroll
                for (int ni = 0; ni < 8; ++ni) {
                    const int c = colbase + ni * 8 + 2 * lc;
                    float2 sc = *(const float2*)(g_scale + c);
                    float vx = acc[mi][ni][hf * 2 + 0] + brow[ni * 8 + 2 * lc];
                    float vy = acc[mi][ni][hf * 2 + 1] + brow[ni * 8 + 2 * lc + 1];
                    float tx = (fmaxf(vx, 0.f) + 1e-6f) / sc.x;
                    float ty = (fmaxf(vy, 0.f) + 1e-6f) / sc.y;
                    float tx2 = tx * tx, ty2 = ty * ty;
                    s2 += tx2 + ty2;
                    s6 += tx2 * tx2 * tx2 + ty2 * ty2 * ty2;
                    *(__half2*)(Hr + ni * 8 + 2 * lc) =
                        __floats2half2_rn(tx * tx2, ty * ty2);   // t^3
                }
                s2 += __shfl_xor_sync(0xffffffffu, s2, 1);
                s6 += __shfl_xor_sync(0xffffffffu, s6, 1);
                s2 += __shfl_xor_sync(0xffffffffu, s2, 2);
                s6 += __shfl_xor_sync(0xffffffffu, s6, 2);
                if (lc == 0)
                    fpart[(size_t)r * 16 + slot] = make_float2(s2, s6);
            }
        }
    }
}

// ---------------------------------------------------------------------------
// Per-row focus factor: r = sqrt(sum t^2) * rsqrt(sum t^6)
// ---------------------------------------------------------------------------
__global__ void __launch_bounds__(256) focus_finalize_kernel() {
    const int idx = blockIdx.x * 256 + threadIdx.x;   // 0..2*MM-1
    const int seg = idx >> 14;                        // MM = 2^14
    const int r = idx & (MM - 1);
    const float2* fp = (seg ? g_fk : g_fq) + (size_t)r * 16;
    float S2 = 0.f, S6 = 0.f;
#pragma unroll
    for (int i = 0; i < 16; ++i) {
        float2 v = fp[i];
        S2 += v.x; S6 += v.y;
    }
    g_r[idx] = sqrtf(S2) * rsqrtf(S6);
}

// ---------------------------------------------------------------------------
// Per-head partial kv = u_K^T V and ksum(u_K) over a slice of N.
// u = t3 * r_k[row] at smem fill (t3 already cubed); packed f32x2 FMA inner.
// ---------------------------------------------------------------------------
__global__ void __launch_bounds__(256) kv_part_kernel() {
    const int bh = blockIdx.x;
    const int chunk = blockIdx.y;
    const int b = bh >> 4, h = bh & 15;
    __shared__ float Ks[64][68];
    __shared__ float Vs[64][68];
    __shared__ float kred[4][64];
    const int tid = threadIdx.x;
    const int tr = tid >> 4, tc = tid & 15;
    const int lr = tid >> 4;
    const int lc4 = (tid & 15) * 4;

    uint64_t acc2[4][2];
#pragma unroll
    for (int i = 0; i < 4; ++i) { acc2[i][0] = 0ull; acc2[i][1] = 0ull; }
    float kpart = 0.f;
    const int scol = tid & 63, srg = tid >> 6;

    const int nlo = chunk * (NN / KVSPLIT);
    const int nhi = nlo + (NN / KVSPLIT);

    for (int n0 = nlo; n0 < nhi; n0 += 64) {
#pragma unroll
        for (int i = 0; i < 4; ++i) {
            const int r = lr + i * 16;
            const int grow = b * NN + n0 + r;
            const size_t off = (size_t)grow * CC + h * DD + lc4;
            const float rk = g_r[MM + grow];
            uint2 uk = *(const uint2*)(g_kh + off);
            uint2 uv = *(const uint2*)(g_vh + off);
            float2 k01 = __half22float2(*(__half2*)&uk.x);
            float2 k23 = __half22float2(*(__half2*)&uk.y);
            float2 v01 = __half22float2(*(__half2*)&uv.x);
            float2 v23 = __half22float2(*(__half2*)&uv.y);
            Ks[r][lc4 + 0] = k01.x * rk;
            Ks[r][lc4 + 1] = k01.y * rk;
            Ks[r][lc4 + 2] = k23.x * rk;
            Ks[r][lc4 + 3] = k23.y * rk;
            Vs[r][lc4 + 0] = v01.x; Vs[r][lc4 + 1] = v01.y;
            Vs[r][lc4 + 2] = v23.x; Vs[r][lc4 + 3] = v23.y;
        }
        __syncthreads();
#pragma unroll
        for (int kk = 0; kk < 64; ++kk) {
            float2 a01 = *(const float2*)&Ks[kk][tr * 4];
            float2 a23 = *(const float2*)&Ks[kk][tr * 4 + 2];
            float2 b01 = *(const float2*)&Vs[kk][tc * 4];
            float2 b23 = *(const float2*)&Vs[kk][tc * 4 + 2];
            const uint64_t bv0 = pack2(b01.x, b01.y);
            const uint64_t bv1 = pack2(b23.x, b23.y);
            const uint64_t a0 = pack2(a01.x, a01.x);
            const uint64_t a1 = pack2(a01.y, a01.y);
            const uint64_t a2 = pack2(a23.x, a23.x);
            const uint64_t a3 = pack2(a23.y, a23.y);
            ffma2(acc2[0][0], a0, bv0); ffma2(acc2[0][1], a0, bv1);
            ffma2(acc2[1][0], a1, bv0); ffma2(acc2[1][1], a1, bv1);
            ffma2(acc2[2][0], a2, bv0); ffma2(acc2[2][1], a2, bv1);
            ffma2(acc2[3][0], a3, bv0); ffma2(acc2[3][1], a3, bv1);
        }
#pragma unroll
        for (int r = 0; r < 16; ++r) kpart += Ks[srg * 16 + r][scol];
        __syncthreads();
    }
    kred[srg][scol] = kpart;
    __syncthreads();
    const size_t pb = (size_t)(bh * KVSPLIT + chunk);
    if (tid < 64)
        g_ksp[pb * DD + tid] = kred[0][tid] + kred[1][tid] + kred[2][tid] + kred[3][tid];
#pragma unroll
    for (int i = 0; i < 4; ++i) {
#pragma unroll
        for (int jp = 0; jp < 2; ++jp) {
            float2 u = unpack2(acc2[i][jp]);
            g_kvp[pb * 4096 + (tr * 4 + i) * 64 + tc * 4 + jp * 2 + 0] = u.x;
            g_kvp[pb * 4096 + (tr * 4 + i) * 64 + tc * 4 + jp * 2 + 1] = u.y;
        }
    }
}

__global__ void __launch_bounds__(256) kv_reduce_kernel() {
    const int bh = blockIdx.x;
    const int tid = threadIdx.x;
    for (int idx = tid; idx < 4096; idx += 256) {
        float s = 0.f;
#pragma unroll
        for (int c = 0; c < KVSPLIT; ++c)
            s += g_kvp[(size_t)(bh * KVSPLIT + c) * 4096 + idx];
        g_kv[(size_t)bh * 4096 + idx] = s;
    }
    if (tid < 64) {
        float s = 0.f;
#pragma unroll
        for (int c = 0; c < KVSPLIT; ++c)
            s += g_ksp[(size_t)(bh * KVSPLIT + c) * DD + tid];
        g_ksum[bh * DD + tid] = s;
    }
}

// ---------------------------------------------------------------------------
// Fused: o = (u_q @ kv) * z + depthwise-conv5(v) + dwc bias; writes half g_oh.
// u_q = t3 * r_q into smem once; f32x2 FMA inner loops, 2 rows per step.
// ---------------------------------------------------------------------------
__global__ void __launch_bounds__(256) o_dwc_kernel(const float* __restrict__ w,
                                                    const float* __restrict__ bias) {
    const int bh = blockIdx.y;
    const int b = bh >> 4, h = bh & 15;
    const int n0 = blockIdx.x * 64;
    __shared__ float qs[64][66];       // u_q tile
    __shared__ float2 kvf2[64][32];    // kv as column pairs
    __shared__ uint4 vsl4[68][8];      // v slice [n0-2, n0+66) x 64 ch (half)
    __shared__ float ks[64];
    const int tid = threadIdx.x;
    const int lane = tid & 31, warp = tid >> 5;

    for (int idx = tid; idx < 1024; idx += 256)
        ((uint4*)kvf2)[idx] = ((const uint4*)(g_kv + (size_t)bh * 4096))[idx];
    if (tid < 64) ks[tid] = g_ksum[bh * DD + tid];
    for (int idx = tid; idx < 68 * 8; idx += 256) {
        const int row = idx >> 3, seg = idx & 7;
        const int n = n0 - 2 + row;
        uint4 val = make_uint4(0u, 0u, 0u, 0u);
        if (n >= 0 && n < NN)
            val = *(const uint4*)(g_vh + (size_t)(b * NN + n) * CC + h * DD + seg * 8);
        vsl4[row][seg] = val;
    }
    for (int idx = tid; idx < 2048; idx += 256) {
        const int row = idx >> 5, c = idx & 31;
        const int gr = b * NN + n0 + row;
        const float rq = g_r[gr];
        __half2 hv = *(const __half2*)(g_qh + (size_t)gr * CC + h * DD + 2 * c);
        float2 t = __half22float2(hv);
        qs[row][2 * c + 0] = t.x * rq;
        qs[row][2 * c + 1] = t.y * rq;
    }
    __syncthreads();

    const __half* vsh = (const __half*)vsl4;   // [68][64]
    const int c0 = h * DD + 2 * lane;          // column pair base
    uint64_t wp[5];
#pragma unroll
    for (int j = 0; j < 5; ++j)
        wp[j] = pack2(w[c0 * KER + j], w[(c0 + 1) * KER + j]);
    const uint64_t bp = pack2(bias[c0], bias[c0 + 1]);
    const float2 ks2 = *(const float2*)&ks[2 * lane];

    for (int rr = 0; rr < 4; ++rr) {
        const int li0 = warp * 8 + rr * 2, li1 = li0 + 1;
        float2 q0p = *(const float2*)&qs[li0][2 * lane];
        float2 q1p = *(const float2*)&qs[li1][2 * lane];
        float zp0 = q0p.x * ks2.x + q0p.y * ks2.y;
        float zp1 = q1p.x * ks2.x + q1p.y * ks2.y;
#pragma unroll
        for (int o = 16; o; o >>= 1) {
            zp0 += __shfl_xor_sync(0xffffffffu, zp0, o);
            zp1 += __shfl_xor_sync(0xffffffffu, zp1, o);
        }
        const float z0 = 1.0f / (zp0 + 1e-6f);
        const float z1 = 1.0f / (zp1 + 1e-6f);

        uint64_t acc0 = 0ull, acc1 = 0ull;
#pragma unroll 16
        for (int d = 0; d < 64; ++d) {
            const float a0 = qs[li0][d];
            const float a1 = qs[li1][d];
            float2 kv = kvf2[d][lane];
            const uint64_t kvu = pack2(kv.x, kv.y);
            ffma2(acc0, pack2(a0, a0), kvu);
            ffma2(acc1, pack2(a1, a1), kvu);
        }

        uint64_t d0 = bp, d1 = bp;
#pragma unroll
        for (int j = 0; j < 5; ++j) {
            float2 v0 = __half22float2(*(const __half2*)(vsh + (li0 + j) * 64 + 2 * lane));
            float2 v1 = __half22float2(*(const __half2*)(vsh + (li1 + j) * 64 + 2 * lane));
            ffma2(d0, wp[j], pack2(v0.x, v0.y));
            ffma2(d1, wp[j], pack2(v1.x, v1.y));
        }

        float2 A0 = unpack2(acc0), A1 = unpack2(acc1);
        float2 D0 = unpack2(d0), D1 = unpack2(d1);
        __half* o0 = g_oh + (size_t)(b * NN + n0 + li0) * CC + c0;
        __half* o1 = g_oh + (size_t)(b * NN + n0 + li1) * CC + c0;
        *(__half2*)o0 = __floats2half2_rn(fmaf(A0.x, z0, D0.x), fmaf(A0.y, z0, D0.y));
        *(__half2*)o1 = __floats2half2_rn(fmaf(A1.x, z1, D1.x), fmaf(A1.y, z1, D1.y));
    }
}

// ---------------------------------------------------------------------------
// Launch (QKV GEMM is the 4th launch -> ncu capture slot)
// ---------------------------------------------------------------------------
extern "C" void kernel_launch(void* const* d_in, const int* in_sizes, int n_in,
                              void* d_out, int out_size) {
    const float* x       = (const float*)d_in[0];
    const float* gamma   = (const float*)d_in[1];
    const float* beta    = (const float*)d_in[2];
    const float* Wqkv    = (const float*)d_in[3];
    const float* bqkv    = (const float*)d_in[4];
    const float* scale_p = (const float*)d_in[5];
    const float* dwc_w   = (const float*)d_in[6];
    const float* dwc_b   = (const float*)d_in[7];
    const float* Wproj   = (const float*)d_in[8];
    const float* bproj   = (const float*)d_in[9];
    float* out = (float*)d_out;

    __half* xh_ptr;  cudaGetSymbolAddress((void**)&xh_ptr, g_xh);
    __half* whq_ptr; cudaGetSymbolAddress((void**)&whq_ptr, g_whq);
    __half* whp_ptr; cudaGetSymbolAddress((void**)&whp_ptr, g_whp);
    __half* oh_ptr;  cudaGetSymbolAddress((void**)&oh_ptr, g_oh);

    cudaFuncSetAttribute(gemm_hmma<true>,  cudaFuncAttributeMaxDynamicSharedMemorySize, GEMM_SMEM_TOT);
    cudaFuncSetAttribute(gemm_hmma<false>, cudaFuncAttributeMaxDynamicSharedMemorySize, GEMM_SMEM_TOT);

    // 1-2. BN statistics (fused with x -> half)
    bnf2h_kernel<<<256, 256>>>(x, xh_ptr);
    bn_finalize_kernel<<<4, 256>>>(gamma, beta, scale_p);

    // 3. Fused prep: Wqkv transpose (BN scale folded) + bias partials
    prep_kernel<<<dim3(96, 32, 2), 256>>>(Wqkv);

    // 4. QKV GEMM (fused focus t^3 epilogue; bias built in smem from partials)
    gemm_hmma<true><<<dim3(K3 / 128, MM / 128), 256, GEMM_SMEM_TOT>>>(
        xh_ptr, whq_ptr, bqkv, (float*)nullptr, K3, CC);

    // 5. Per-row focus factors
    focus_finalize_kernel<<<2 * MM / 256, 256>>>();

    // 6. Wproj transpose
    transpose_h_kernel<<<dim3(CC / 32, CC / 32), 256>>>(Wproj, whp_ptr, CC, CC);

    // 7-8. Per-head kv = u_K^T V and ksum (split over N, then reduce)
    kv_part_kernel<<<dim3(BB * HH, KVSPLIT), 256>>>();
    kv_reduce_kernel<<<BB * HH, 256>>>();

    // 9. Fused attention output + depthwise conv -> half g_oh
    o_dwc_kernel<<<dim3(NN / 64, BB * HH), 256>>>(dwc_w, dwc_b);

    // 10. Projection GEMM (f32 out)
    gemm_hmma<false><<<dim3(CC / 128, MM / 128), 256, GEMM_SMEM_TOT>>>(
        oh_ptr, whp_ptr, bproj, out, CC, CC);
}

// round 15
// speedup vs baseline: 1.4117x; 1.1052x over previous
#include <cuda_runtime.h>
#include <cuda_fp16.h>
#include <cstdint>

// Problem constants
#define BB 8
#define NN 2048
#define CC 1024
#define HH 16
#define DD 64
#define MM (BB * NN)        // 16384 rows
#define K3 (3 * CC)         // 3072
#define KER 5
#define QK2 (2 * CC)        // 2048

// GEMM tiling: fp16 mma.sync m16n8k16 + ldmatrix, BK=32, 5-stage cp.async ring,
// prefetch distance 3, barrier every 2 iterations.
#define BKH 32                        // K halves per stage = 64 B/row
#define SSTRIDE 80                    // smem row stride bytes (64 + 16 pad, conflict-free)
#define HTILE (128 * SSTRIDE)         // 10240 per operand tile
#define HSTAGE (2 * HTILE)            // A + B = 20480
#define NSTG 5
#define GEMM_SMEM5 (NSTG * HSTAGE)    // 102400
#define GEMM_SMEM_TOT (GEMM_SMEM5 + 512)

#define KVSPLIT 8
#define BFSPLIT 16

// ---------------------------------------------------------------------------
// Scratch (device globals; no allocations allowed)
// ---------------------------------------------------------------------------
__device__ __half g_vh[(size_t)MM * CC];        // v half
__device__ __half g_qh[(size_t)MM * CC];        // q t^3 half (focus, pre-normalization)
__device__ __half g_kh[(size_t)MM * CC];        // k t^3 half
__device__ __half g_oh[(size_t)MM * CC];        // attention+dwc (half, proj A operand)
__device__ __half g_xh[(size_t)MM * CC];        // x in half
__device__ __half g_whq[(size_t)K3 * CC];       // (a ⊙ W_qkv)^T half
__device__ __half g_whp[(size_t)CC * CC];       // W_proj^T half
__device__ float2 g_fq[(size_t)MM * 16];        // q row partials (sum t^2, sum t^6)
__device__ float2 g_fk[(size_t)MM * 16];        // k row partials
__device__ float  g_r[2 * MM];                  // per-row focus factor (q then k)
__device__ float  g_kv[BB * HH * DD * DD];
__device__ float  g_ksum[BB * HH * DD];
__device__ float  g_kvp[(size_t)BB * HH * KVSPLIT * DD * DD];
__device__ float  g_ksp[BB * HH * KVSPLIT * DD];
__device__ float  g_part[256 * 2 * CC];
__device__ float  g_bp[BFSPLIT * K3];
__device__ float  g_a[CC], g_shift[CC], g_scale[CC];

// ---------------------------------------------------------------------------
// PTX helpers
// ---------------------------------------------------------------------------
__device__ __forceinline__ uint32_t smem_u32(const void* p) {
    uint32_t a;
    asm("{ .reg .u64 t; cvta.to.shared.u64 t, %1; cvt.u32.u64 %0, t; }" : "=r"(a) : "l"(p));
    return a;
}
__device__ __forceinline__ void cp_async16(uint32_t saddr, const void* gptr) {
    asm volatile("cp.async.cg.shared.global [%0], [%1], 16;" :: "r"(saddr), "l"(gptr) : "memory");
}
__device__ __forceinline__ void cp_commit() {
    asm volatile("cp.async.commit_group;" ::: "memory");
}
template <int N>
__device__ __forceinline__ void cp_wait() {
    asm volatile("cp.async.wait_group %0;" :: "n"(N) : "memory");
}
__device__ __forceinline__ void ldm_x4(uint32_t* r, uint32_t addr) {
    asm volatile("ldmatrix.sync.aligned.m8n8.x4.shared.b16 {%0,%1,%2,%3}, [%4];"
                 : "=r"(r[0]), "=r"(r[1]), "=r"(r[2]), "=r"(r[3]) : "r"(addr));
}
__device__ __forceinline__ void mma_f16(float* c, const uint32_t* a, const uint32_t* b) {
    asm volatile(
        "mma.sync.aligned.m16n8k16.row.col.f32.f16.f16.f32 "
        "{%0,%1,%2,%3}, {%4,%5,%6,%7}, {%8,%9}, {%0,%1,%2,%3};"
        : "+f"(c[0]), "+f"(c[1]), "+f"(c[2]), "+f"(c[3])
        : "r"(a[0]), "r"(a[1]), "r"(a[2]), "r"(a[3]), "r"(b[0]), "r"(b[1]));
}
// Packed f32x2 (Blackwell): one instruction, two fp32 FMAs
__device__ __forceinline__ void ffma2(uint64_t& c, uint64_t a, uint64_t b) {
    asm("fma.rn.f32x2 %0, %1, %2, %0;" : "+l"(c) : "l"(a), "l"(b));
}
__device__ __forceinline__ uint64_t pack2(float lo, float hi) {
    uint64_t r;
    asm("mov.b64 %0, {%1, %2};" : "=l"(r) : "f"(lo), "f"(hi));
    return r;
}
__device__ __forceinline__ float2 unpack2(uint64_t v) {
    float2 r;
    asm("mov.b64 {%0, %1}, %2;" : "=f"(r.x), "=f"(r.y) : "l"(v));
    return r;
}

// ---------------------------------------------------------------------------
// BN stats partial sums fused with x -> half conversion.
// ---------------------------------------------------------------------------
__global__ void __launch_bounds__(256) bnf2h_kernel(const float* __restrict__ x,
                                                    __half* __restrict__ xh) {
    const int blk = blockIdx.x;
    const int tid = threadIdx.x;
    const int r0 = blk * 64;
    float s[4] = {0.f, 0.f, 0.f, 0.f};
    float ss[4] = {0.f, 0.f, 0.f, 0.f};
    for (int r = 0; r < 64; ++r) {
        const size_t rowo = (size_t)(r0 + r) * CC;
        float4 v = *(const float4*)(x + rowo + tid * 4);
        s[0] += v.x; ss[0] += v.x * v.x;
        s[1] += v.y; ss[1] += v.y * v.y;
        s[2] += v.z; ss[2] += v.z * v.z;
        s[3] += v.w; ss[3] += v.w * v.w;
        __half2 h0 = __floats2half2_rn(v.x, v.y);
        __half2 h1 = __floats2half2_rn(v.z, v.w);
        uint2 u;
        u.x = *(uint32_t*)&h0; u.y = *(uint32_t*)&h1;
        *(uint2*)(xh + rowo + tid * 4) = u;
    }
#pragma unroll
    for (int j = 0; j < 4; ++j) {
        g_part[(size_t)blk * 2048 + tid * 4 + j] = s[j];
        g_part[(size_t)blk * 2048 + 1024 + tid * 4 + j] = ss[j];
    }
}

__global__ void bn_finalize_kernel(const float* __restrict__ gamma,
                                   const float* __restrict__ beta,
                                   const float* __restrict__ scale_p) {
    const int ch = blockIdx.x * 256 + threadIdx.x;
    float s = 0.f, ss = 0.f;
    for (int b = 0; b < 256; ++b) {
        s += g_part[(size_t)b * 2048 + ch];
        ss += g_part[(size_t)b * 2048 + 1024 + ch];
    }
    const float inv = 1.0f / (float)MM;
    float mean = s * inv;
    float var = ss * inv - mean * mean;
    float rstd = rsqrtf(var + 1e-5f);
    float a = rstd * gamma[ch];
    g_a[ch] = a;
    g_shift[ch] = beta[ch] - mean * a;
    float p = scale_p[ch];
    g_scale[ch] = fmaxf(p, 0.f) + log1pf(expf(-fabsf(p)));
}

// ---------------------------------------------------------------------------
// Prep (fused): z=0 -> transpose Wqkv (K,N)->(N,K) half with g_a folded;
//               z=1 -> biasfold partials
// ---------------------------------------------------------------------------
__global__ void __launch_bounds__(256) prep_kernel(const float* __restrict__ W) {
    __shared__ float t[32][33];
    if (blockIdx.z == 0) {
        const int n0 = blockIdx.x * 32, k0 = blockIdx.y * 32;
        const int tx = threadIdx.x & 31, ty = threadIdx.x >> 5;
#pragma unroll
        for (int i = 0; i < 4; ++i)
            t[ty + i * 8][tx] = W[(size_t)(k0 + ty + i * 8) * K3 + n0 + tx];
        __syncthreads();
        const float ak = g_a[k0 + tx];
#pragma unroll
        for (int i = 0; i < 4; ++i)
            g_whq[(size_t)(n0 + ty + i * 8) * CC + k0 + tx] =
                __float2half_rn(ak * t[tx][ty + i * 8]);
    } else {
        if (blockIdx.x < 12 && blockIdx.y < 16) {
            const int n = blockIdx.x * 256 + threadIdx.x;
            const int k0 = blockIdx.y * (CC / BFSPLIT);
            float s = 0.f;
#pragma unroll 8
            for (int k = 0; k < CC / BFSPLIT; ++k)
                s += g_shift[k0 + k] * W[(size_t)(k0 + k) * K3 + n];
            g_bp[(size_t)blockIdx.y * K3 + n] = s;
        }
    }
}

// ---------------------------------------------------------------------------
// Transpose W (K,N) -> Wt (N,K) half (no scale) — for Wproj.
// ---------------------------------------------------------------------------
__global__ void __launch_bounds__(256) transpose_h_kernel(
    const float* __restrict__ W, __half* __restrict__ Wt, int K, int N)
{
    __shared__ float t[32][33];
    const int n0 = blockIdx.x * 32, k0 = blockIdx.y * 32;
    const int tx = threadIdx.x & 31, ty = threadIdx.x >> 5;
#pragma unroll
    for (int i = 0; i < 4; ++i)
        t[ty + i * 8][tx] = W[(size_t)(k0 + ty + i * 8) * N + n0 + tx];
    __syncthreads();
#pragma unroll
    for (int i = 0; i < 4; ++i)
        Wt[(size_t)(n0 + ty + i * 8) * K + k0 + tx] = __float2half_rn(t[tx][ty + i * 8]);
}

// ---------------------------------------------------------------------------
// fp16 mma.sync GEMM. Block 128x128, BK=32, 8 warps (4m x 2n), warp 32x64,
// 5-stage ring, prefetch distance 3, barrier every 2 iterations.
// SPLIT (QKV): bias built in smem from bias[] + 16 g_bp partials.
//   cols < CC  -> focus t^3 half to g_qh + row partials g_fq
//   cols < QK2 -> focus t^3 half to g_kh + row partials g_fk
//   cols >= QK2-> plain half to g_vh
// !SPLIT (proj): f32 to Cf, bias read directly.
// ---------------------------------------------------------------------------
template <bool SPLIT>
__global__ void __launch_bounds__(256, 2) gemm_hmma(
    const __half* __restrict__ A, const __half* __restrict__ Bt,
    const float* __restrict__ bias, float* __restrict__ Cf,
    int Ndim, int Kdim)
{
    extern __shared__ char sm[];
    const int tid = threadIdx.x;
    const int lane = tid & 31, w = tid >> 5;
    const int wm = w & 3, wn = w >> 2;
    const int row0 = blockIdx.y * 128, col0 = blockIdx.x * 128;
    const uint32_t sbase = smem_u32(sm);
    float* sbias = (float*)(sm + GEMM_SMEM5);

    if (SPLIT && tid < 128) {
        const int c = col0 + tid;
        float s = bias[c];
#pragma unroll
        for (int i = 0; i < BFSPLIT; ++i) s += g_bp[(size_t)i * K3 + c];
        sbias[tid] = s;
    }

    // loader: thread -> row tid>>1, 32B half (tid&1): two 16B chunks
    const int lrow = tid >> 1, lh = tid & 1;
    const __half* gA = A + (size_t)(row0 + lrow) * Kdim + lh * 16;
    const __half* gB = Bt + (size_t)(col0 + lrow) * Kdim + lh * 16;
    const uint32_t sOff = (uint32_t)(lrow * SSTRIDE + lh * 32);

    float acc[2][8][4];
#pragma unroll
    for (int mi = 0; mi < 2; ++mi)
#pragma unroll
        for (int ni = 0; ni < 8; ++ni)
#pragma unroll
            for (int j = 0; j < 4; ++j) acc[mi][ni][j] = 0.f;

    const uint32_t aoff0 = (uint32_t)((wm * 32 + (lane & 15)) * SSTRIDE + (lane >> 4) * 16);
    const uint32_t boff0 = (uint32_t)((wn * 64 + (lane & 7) + (lane >> 4) * 8) * SSTRIDE +
                                      ((lane >> 3) & 1) * 16);

    const int T = Kdim / BKH;   // 32 (even)

    // prologue: stages 0..2
#pragma unroll
    for (int s = 0; s < 3; ++s) {
        const uint32_t sa = sbase + s * HSTAGE + sOff;
        const uint32_t sb = sa + HTILE;
        const __half* ga = gA + s * BKH;
        const __half* gb = gB + s * BKH;
        cp_async16(sa, ga);
        cp_async16(sa + 16, ga + 8);
        cp_async16(sb, gb);
        cp_async16(sb + 16, gb + 8);
        cp_commit();
    }

    for (int t = 0; t < T; t += 2) {
        cp_wait<1>();            // stages t and t+1 resident
        __syncthreads();

        // --- iter t: prefetch stage t+3, compute buf t%5 ---
        if (t + 3 < T) {
            const int sidx = (t + 3) % NSTG;
            const uint32_t sa = sbase + sidx * HSTAGE + sOff;
            const uint32_t sb = sa + HTILE;
            const __half* ga = gA + (t + 3) * BKH;
            const __half* gb = gB + (t + 3) * BKH;
            cp_async16(sa, ga);
            cp_async16(sa + 16, ga + 8);
            cp_async16(sb, gb);
            cp_async16(sb + 16, gb + 8);
        }
        cp_commit();
        {
            const int buf = t % NSTG;
            const uint32_t abase = sbase + buf * HSTAGE + aoff0;
            const uint32_t bbase = sbase + buf * HSTAGE + HTILE + boff0;
#pragma unroll
            for (int ks = 0; ks < 2; ++ks) {
                uint32_t af[2][4];
                uint32_t bf[4][4];
#pragma unroll
                for (int mi = 0; mi < 2; ++mi)
                    ldm_x4(af[mi], abase + mi * 16 * SSTRIDE + ks * 32);
#pragma unroll
                for (int nt = 0; nt < 4; ++nt)
                    ldm_x4(bf[nt], bbase + nt * 16 * SSTRIDE + ks * 32);
#pragma unroll
                for (int mi = 0; mi < 2; ++mi)
#pragma unroll
                    for (int ni = 0; ni < 8; ++ni)
                        mma_f16(acc[mi][ni], af[mi], &bf[ni >> 1][(ni & 1) * 2]);
            }
        }

        // --- iter t+1: prefetch stage t+4, compute buf (t+1)%5 ---
        if (t + 4 < T) {
            const int sidx = (t + 4) % NSTG;
            const uint32_t sa = sbase + sidx * HSTAGE + sOff;
            const uint32_t sb = sa + HTILE;
            const __half* ga = gA + (t + 4) * BKH;
            const __half* gb = gB + (t + 4) * BKH;
            cp_async16(sa, ga);
            cp_async16(sa + 16, ga + 8);
            cp_async16(sb, gb);
            cp_async16(sb + 16, gb + 8);
        }
        cp_commit();
        {
            const int buf = (t + 1) % NSTG;
            const uint32_t abase = sbase + buf * HSTAGE + aoff0;
            const uint32_t bbase = sbase + buf * HSTAGE + HTILE + boff0;
#pragma unroll
            for (int ks = 0; ks < 2; ++ks) {
                uint32_t af[2][4];
                uint32_t bf[4][4];
#pragma unroll
                for (int mi = 0; mi < 2; ++mi)
                    ldm_x4(af[mi], abase + mi * 16 * SSTRIDE + ks * 32);
#pragma unroll
                for (int nt = 0; nt < 4; ++nt)
                    ldm_x4(bf[nt], bbase + nt * 16 * SSTRIDE + ks * 32);
#pragma unroll
                for (int mi = 0; mi < 2; ++mi)
#pragma unroll
                    for (int ni = 0; ni < 8; ++ni)
                        mma_f16(acc[mi][ni], af[mi], &bf[ni >> 1][(ni & 1) * 2]);
            }
        }
    }
    __syncthreads();

    // epilogue
    const int lr = lane >> 2, lc = lane & 3;
    const float* brow = SPLIT ? (sbias + wn * 64) : (bias + col0 + wn * 64);

    if (!SPLIT) {
#pragma unroll
        for (int mi = 0; mi < 2; ++mi) {
            const int mrow = row0 + wm * 32 + mi * 16 + lr;
#pragma unroll
            for (int hf = 0; hf < 2; ++hf) {
                float* Cr = Cf + (size_t)(mrow + hf * 8) * Ndim + col0 + wn * 64;
#pragma unroll
                for (int ni = 0; ni < 8; ++ni) {
                    float2 o;
                    o.x = acc[mi][ni][hf * 2 + 0] + brow[ni * 8 + 2 * lc];
                    o.y = acc[mi][ni][hf * 2 + 1] + brow[ni * 8 + 2 * lc + 1];
                    *(float2*)(Cr + ni * 8 + 2 * lc) = o;
                }
            }
        }
    } else if (col0 >= QK2) {
        // v mode: plain half
#pragma unroll
        for (int mi = 0; mi < 2; ++mi) {
            const int mrow = row0 + wm * 32 + mi * 16 + lr;
#pragma unroll
            for (int hf = 0; hf < 2; ++hf) {
                __half* Hr = g_vh + (size_t)(mrow + hf * 8) * CC + (col0 - QK2) + wn * 64;
#pragma unroll
                for (int ni = 0; ni < 8; ++ni) {
                    float ox = acc[mi][ni][hf * 2 + 0] + brow[ni * 8 + 2 * lc];
                    float oy = acc[mi][ni][hf * 2 + 1] + brow[ni * 8 + 2 * lc + 1];
                    *(__half2*)(Hr + ni * 8 + 2 * lc) = __floats2half2_rn(ox, oy);
                }
            }
        }
    } else {
        // q/k focus mode: t = (relu(val)+1e-6)/scale; store t^3 as half + partials
        const int seg = (col0 >= CC) ? 1 : 0;
        const int colbase = (col0 - seg * CC) + wn * 64;
        const int slot = ((col0 - seg * CC) >> 7) * 2 + wn;   // 0..15
        __half* Hbase = seg ? g_kh : g_qh;
        float2* fpart = seg ? g_fk : g_fq;
#pragma unroll
        for (int mi = 0; mi < 2; ++mi) {
#pragma unroll
            for (int hf = 0; hf < 2; ++hf) {
                const int r = row0 + wm * 32 + mi * 16 + lr + hf * 8;
                __half* Hr = Hbase + (size_t)r * CC + colbase;
                float s2 = 0.f, s6 = 0.f;
#pragma unroll
                for (int ni = 0; ni < 8; ++ni) {
                    const int c = colbase + ni * 8 + 2 * lc;
                    float2 sc = *(const float2*)(g_scale + c);
                    float vx = acc[mi][ni][hf * 2 + 0] + brow[ni * 8 + 2 * lc];
                    float vy = acc[mi][ni][hf * 2 + 1] + brow[ni * 8 + 2 * lc + 1];
                    float tx = (fmaxf(vx, 0.f) + 1e-6f) / sc.x;
                    float ty = (fmaxf(vy, 0.f) + 1e-6f) / sc.y;
                    float tx2 = tx * tx, ty2 = ty * ty;
                    s2 += tx2 + ty2;
                    s6 += tx2 * tx2 * tx2 + ty2 * ty2 * ty2;
                    *(__half2*)(Hr + ni * 8 + 2 * lc) =
                        __floats2half2_rn(tx * tx2, ty * ty2);   // t^3
                }
                s2 += __shfl_xor_sync(0xffffffffu, s2, 1);
                s6 += __shfl_xor_sync(0xffffffffu, s6, 1);
                s2 += __shfl_xor_sync(0xffffffffu, s2, 2);
                s6 += __shfl_xor_sync(0xffffffffu, s6, 2);
                if (lc == 0)
                    fpart[(size_t)r * 16 + slot] = make_float2(s2, s6);
            }
        }
    }
}

// ---------------------------------------------------------------------------
// Per-row focus factor: r = sqrt(sum t^2) * rsqrt(sum t^6)
// ---------------------------------------------------------------------------
__global__ void __launch_bounds__(256) focus_finalize_kernel() {
    const int idx = blockIdx.x * 256 + threadIdx.x;   // 0..2*MM-1
    const int seg = idx >> 14;                        // MM = 2^14
    const int r = idx & (MM - 1);
    const float2* fp = (seg ? g_fk : g_fq) + (size_t)r * 16;
    float S2 = 0.f, S6 = 0.f;
#pragma unroll
    for (int i = 0; i < 16; ++i) {
        float2 v = fp[i];
        S2 += v.x; S6 += v.y;
    }
    g_r[idx] = sqrtf(S2) * rsqrtf(S6);
}

// ---------------------------------------------------------------------------
// Per-head partial kv = u_K^T V and ksum(u_K) over a slice of N.
// u = t3 * r_k[row] at smem fill (t3 already cubed); packed f32x2 FMA inner.
// ---------------------------------------------------------------------------
__global__ void __launch_bounds__(256) kv_part_kernel() {
    const int bh = blockIdx.x;
    const int chunk = blockIdx.y;
    const int b = bh >> 4, h = bh & 15;
    __shared__ float Ks[64][68];
    __shared__ float Vs[64][68];
    __shared__ float kred[4][64];
    const int tid = threadIdx.x;
    const int tr = tid >> 4, tc = tid & 15;
    const int lr = tid >> 4;
    const int lc4 = (tid & 15) * 4;

    uint64_t acc2[4][2];
#pragma unroll
    for (int i = 0; i < 4; ++i) { acc2[i][0] = 0ull; acc2[i][1] = 0ull; }
    float kpart = 0.f;
    const int scol = tid & 63, srg = tid >> 6;

    const int nlo = chunk * (NN / KVSPLIT);
    const int nhi = nlo + (NN / KVSPLIT);

    for (int n0 = nlo; n0 < nhi; n0 += 64) {
#pragma unroll
        for (int i = 0; i < 4; ++i) {
            const int r = lr + i * 16;
            const int grow = b * NN + n0 + r;
            const size_t off = (size_t)grow * CC + h * DD + lc4;
            const float rk = g_r[MM + grow];
            uint2 uk = *(const uint2*)(g_kh + off);
            uint2 uv = *(const uint2*)(g_vh + off);
            float2 k01 = __half22float2(*(__half2*)&uk.x);
            float2 k23 = __half22float2(*(__half2*)&uk.y);
            float2 v01 = __half22float2(*(__half2*)&uv.x);
            float2 v23 = __half22float2(*(__half2*)&uv.y);
            Ks[r][lc4 + 0] = k01.x * rk;
            Ks[r][lc4 + 1] = k01.y * rk;
            Ks[r][lc4 + 2] = k23.x * rk;
            Ks[r][lc4 + 3] = k23.y * rk;
            Vs[r][lc4 + 0] = v01.x; Vs[r][lc4 + 1] = v01.y;
            Vs[r][lc4 + 2] = v23.x; Vs[r][lc4 + 3] = v23.y;
        }
        __syncthreads();
#pragma unroll
        for (int kk = 0; kk < 64; ++kk) {
            float2 a01 = *(const float2*)&Ks[kk][tr * 4];
            float2 a23 = *(const float2*)&Ks[kk][tr * 4 + 2];
            float2 b01 = *(const float2*)&Vs[kk][tc * 4];
            float2 b23 = *(const float2*)&Vs[kk][tc * 4 + 2];
            const uint64_t bv0 = pack2(b01.x, b01.y);
            const uint64_t bv1 = pack2(b23.x, b23.y);
            const uint64_t a0 = pack2(a01.x, a01.x);
            const uint64_t a1 = pack2(a01.y, a01.y);
            const uint64_t a2 = pack2(a23.x, a23.x);
            const uint64_t a3 = pack2(a23.y, a23.y);
            ffma2(acc2[0][0], a0, bv0); ffma2(acc2[0][1], a0, bv1);
            ffma2(acc2[1][0], a1, bv0); ffma2(acc2[1][1], a1, bv1);
            ffma2(acc2[2][0], a2, bv0); ffma2(acc2[2][1], a2, bv1);
            ffma2(acc2[3][0], a3, bv0); ffma2(acc2[3][1], a3, bv1);
        }
#pragma unroll
        for (int r = 0; r < 16; ++r) kpart += Ks[srg * 16 + r][scol];
        __syncthreads();
    }
    kred[srg][scol] = kpart;
    __syncthreads();
    const size_t pb = (size_t)(bh * KVSPLIT + chunk);
    if (tid < 64)
        g_ksp[pb * DD + tid] = kred[0][tid] + kred[1][tid] + kred[2][tid] + kred[3][tid];
#pragma unroll
    for (int i = 0; i < 4; ++i) {
#pragma unroll
        for (int jp = 0; jp < 2; ++jp) {
            float2 u = unpack2(acc2[i][jp]);
            g_kvp[pb * 4096 + (tr * 4 + i) * 64 + tc * 4 + jp * 2 + 0] = u.x;
            g_kvp[pb * 4096 + (tr * 4 + i) * 64 + tc * 4 + jp * 2 + 1] = u.y;
        }
    }
}

__global__ void __launch_bounds__(256) kv_reduce_kernel() {
    const int bh = blockIdx.x;
    const int tid = threadIdx.x;
    for (int idx = tid; idx < 4096; idx += 256) {
        float s = 0.f;
#pragma unroll
        for (int c = 0; c < KVSPLIT; ++c)
            s += g_kvp[(size_t)(bh * KVSPLIT + c) * 4096 + idx];
        g_kv[(size_t)bh * 4096 + idx] = s;
    }
    if (tid < 64) {
        float s = 0.f;
#pragma unroll
        for (int c = 0; c < KVSPLIT; ++c)
            s += g_ksp[(size_t)(bh * KVSPLIT + c) * DD + tid];
        g_ksum[bh * DD + tid] = s;
    }
}

// ---------------------------------------------------------------------------
// Fused: o = (u_q @ kv) * z + depthwise-conv5(v) + dwc bias; writes half g_oh.
// u_q = t3 * r_q into smem once; f32x2 FMA inner loops, 2 rows per step.
// ---------------------------------------------------------------------------
__global__ void __launch_bounds__(256) o_dwc_kernel(const float* __restrict__ w,
                                                    const float* __restrict__ bias) {
    const int bh = blockIdx.y;
    const int b = bh >> 4, h = bh & 15;
    const int n0 = blockIdx.x * 64;
    __shared__ float qs[64][66];       // u_q tile
    __shared__ float2 kvf2[64][32];    // kv as column pairs
    __shared__ uint4 vsl4[68][8];      // v slice [n0-2, n0+66) x 64 ch (half)
    __shared__ float ks[64];
    const int tid = threadIdx.x;
    const int lane = tid & 31, warp = tid >> 5;

    for (int idx = tid; idx < 1024; idx += 256)
        ((uint4*)kvf2)[idx] = ((const uint4*)(g_kv + (size_t)bh * 4096))[idx];
    if (tid < 64) ks[tid] = g_ksum[bh * DD + tid];
    for (int idx = tid; idx < 68 * 8; idx += 256) {
        const int row = idx >> 3, seg = idx & 7;
        const int n = n0 - 2 + row;
        uint4 val = make_uint4(0u, 0u, 0u, 0u);
        if (n >= 0 && n < NN)
            val = *(const uint4*)(g_vh + (size_t)(b * NN + n) * CC + h * DD + seg * 8);
        vsl4[row][seg] = val;
    }
    for (int idx = tid; idx < 2048; idx += 256) {
        const int row = idx >> 5, c = idx & 31;
        const int gr = b * NN + n0 + row;
        const float rq = g_r[gr];
        __half2 hv = *(const __half2*)(g_qh + (size_t)gr * CC + h * DD + 2 * c);
        float2 t = __half22float2(hv);
        qs[row][2 * c + 0] = t.x * rq;
        qs[row][2 * c + 1] = t.y * rq;
    }
    __syncthreads();

    const __half* vsh = (const __half*)vsl4;   // [68][64]
    const int c0 = h * DD + 2 * lane;          // column pair base
    uint64_t wp[5];
#pragma unroll
    for (int j = 0; j < 5; ++j)
        wp[j] = pack2(w[c0 * KER + j], w[(c0 + 1) * KER + j]);
    const uint64_t bp = pack2(bias[c0], bias[c0 + 1]);
    const float2 ks2 = *(const float2*)&ks[2 * lane];

    for (int rr = 0; rr < 4; ++rr) {
        const int li0 = warp * 8 + rr * 2, li1 = li0 + 1;
        float2 q0p = *(const float2*)&qs[li0][2 * lane];
        float2 q1p = *(const float2*)&qs[li1][2 * lane];
        float zp0 = q0p.x * ks2.x + q0p.y * ks2.y;
        float zp1 = q1p.x * ks2.x + q1p.y * ks2.y;
#pragma unroll
        for (int o = 16; o; o >>= 1) {
            zp0 += __shfl_xor_sync(0xffffffffu, zp0, o);
            zp1 += __shfl_xor_sync(0xffffffffu, zp1, o);
        }
        const float z0 = 1.0f / (zp0 + 1e-6f);
        const float z1 = 1.0f / (zp1 + 1e-6f);

        uint64_t acc0 = 0ull, acc1 = 0ull;
#pragma unroll 16
        for (int d = 0; d < 64; ++d) {
            const float a0 = qs[li0][d];
            const float a1 = qs[li1][d];
            float2 kv = kvf2[d][lane];
            const uint64_t kvu = pack2(kv.x, kv.y);
            ffma2(acc0, pack2(a0, a0), kvu);
            ffma2(acc1, pack2(a1, a1), kvu);
        }

        uint64_t d0 = bp, d1 = bp;
#pragma unroll
        for (int j = 0; j < 5; ++j) {
            float2 v0 = __half22float2(*(const __half2*)(vsh + (li0 + j) * 64 + 2 * lane));
            float2 v1 = __half22float2(*(const __half2*)(vsh + (li1 + j) * 64 + 2 * lane));
            ffma2(d0, wp[j], pack2(v0.x, v0.y));
            ffma2(d1, wp[j], pack2(v1.x, v1.y));
        }

        float2 A0 = unpack2(acc0), A1 = unpack2(acc1);
        float2 D0 = unpack2(d0), D1 = unpack2(d1);
        __half* o0 = g_oh + (size_t)(b * NN + n0 + li0) * CC + c0;
        __half* o1 = g_oh + (size_t)(b * NN + n0 + li1) * CC + c0;
        *(__half2*)o0 = __floats2half2_rn(fmaf(A0.x, z0, D0.x), fmaf(A0.y, z0, D0.y));
        *(__half2*)o1 = __floats2half2_rn(fmaf(A1.x, z1, D1.x), fmaf(A1.y, z1, D1.y));
    }
}

// ---------------------------------------------------------------------------
// Launch (QKV GEMM is the 4th launch -> ncu capture slot)
// ---------------------------------------------------------------------------
extern "C" void kernel_launch(void* const* d_in, const int* in_sizes, int n_in,
                              void* d_out, int out_size) {
    const float* x       = (const float*)d_in[0];
    const float* gamma   = (const float*)d_in[1];
    const float* beta    = (const float*)d_in[2];
    const float* Wqkv    = (const float*)d_in[3];
    const float* bqkv    = (const float*)d_in[4];
    const float* scale_p = (const float*)d_in[5];
    const float* dwc_w   = (const float*)d_in[6];
    const float* dwc_b   = (const float*)d_in[7];
    const float* Wproj   = (const float*)d_in[8];
    const float* bproj   = (const float*)d_in[9];
    float* out = (float*)d_out;

    __half* xh_ptr;  cudaGetSymbolAddress((void**)&xh_ptr, g_xh);
    __half* whq_ptr; cudaGetSymbolAddress((void**)&whq_ptr, g_whq);
    __half* whp_ptr; cudaGetSymbolAddress((void**)&whp_ptr, g_whp);
    __half* oh_ptr;  cudaGetSymbolAddress((void**)&oh_ptr, g_oh);

    cudaFuncSetAttribute(gemm_hmma<true>,  cudaFuncAttributeMaxDynamicSharedMemorySize, GEMM_SMEM_TOT);
    cudaFuncSetAttribute(gemm_hmma<false>, cudaFuncAttributeMaxDynamicSharedMemorySize, GEMM_SMEM_TOT);

    // 1-2. BN statistics (fused with x -> half)
    bnf2h_kernel<<<256, 256>>>(x, xh_ptr);
    bn_finalize_kernel<<<4, 256>>>(gamma, beta, scale_p);

    // 3. Fused prep: Wqkv transpose (BN scale folded) + bias partials
    prep_kernel<<<dim3(96, 32, 2), 256>>>(Wqkv);

    // 4. QKV GEMM (fused focus t^3 epilogue; bias built in smem from partials)
    gemm_hmma<true><<<dim3(K3 / 128, MM / 128), 256, GEMM_SMEM_TOT>>>(
        xh_ptr, whq_ptr, bqkv, (float*)nullptr, K3, CC);

    // 5. Per-row focus factors
    focus_finalize_kernel<<<2 * MM / 256, 256>>>();

    // 6. Wproj transpose
    transpose_h_kernel<<<dim3(CC / 32, CC / 32), 256>>>(Wproj, whp_ptr, CC, CC);

    // 7-8. Per-head kv = u_K^T V and ksum (split over N, then reduce)
    kv_part_kernel<<<dim3(BB * HH, KVSPLIT), 256>>>();
    kv_reduce_kernel<<<BB * HH, 256>>>();

    // 9. Fused attention output + depthwise conv -> half g_oh
    o_dwc_kernel<<<dim3(NN / 64, BB * HH), 256>>>(dwc_w, dwc_b);

    // 10. Projection GEMM (f32 out)
    gemm_hmma<false><<<dim3(CC / 128, MM / 128), 256, GEMM_SMEM_TOT>>>(
        oh_ptr, whp_ptr, bproj, out, CC, CC);
}

// round 16
// speedup vs baseline: 1.4251x; 1.0096x over previous
#include <cuda_runtime.h>
#include <cuda_fp16.h>
#include <cstdint>

// Problem constants
#define BB 8
#define NN 2048
#define CC 1024
#define HH 16
#define DD 64
#define MM (BB * NN)        // 16384 rows
#define K3 (3 * CC)         // 3072
#define KER 5
#define QK2 (2 * CC)        // 2048

// GEMM tiling: fp16 mma.sync m16n8k16 + ldmatrix, BK=32, 5-stage cp.async ring,
// prefetch distance 3, barrier every 2 iterations.
#define BKH 32                        // K halves per stage = 64 B/row
#define SSTRIDE 80                    // smem row stride bytes (64 + 16 pad, conflict-free)
#define HTILE (128 * SSTRIDE)         // 10240 per operand tile
#define HSTAGE (2 * HTILE)            // A + B = 20480
#define NSTG 5
#define GEMM_SMEM5 (NSTG * HSTAGE)    // 102400
#define GEMM_SMEM_TOT (GEMM_SMEM5 + 512)

#define KVSPLIT 16
#define BFSPLIT 16
#define BNBLK 512

// ---------------------------------------------------------------------------
// Scratch (device globals; no allocations allowed)
// ---------------------------------------------------------------------------
__device__ __half g_vh[(size_t)MM * CC];        // v half
__device__ __half g_qh[(size_t)MM * CC];        // q t^3 half (focus, pre-normalization)
__device__ __half g_kh[(size_t)MM * CC];        // k t^3 half
__device__ __half g_oh[(size_t)MM * CC];        // attention+dwc (half, proj A operand)
__device__ __half g_xh[(size_t)MM * CC];        // x in half
__device__ __half g_whq[(size_t)K3 * CC];       // (a ⊙ W_qkv)^T half
__device__ __half g_whp[(size_t)CC * CC];       // W_proj^T half
__device__ float2 g_fq[(size_t)MM * 16];        // q row partials (sum t^2, sum t^6)
__device__ float2 g_fk[(size_t)MM * 16];        // k row partials
__device__ float  g_r[2 * MM];                  // per-row focus factor (q then k)
__device__ float  g_kv[BB * HH * DD * DD];
__device__ float  g_ksum[BB * HH * DD];
__device__ float  g_kvp[(size_t)BB * HH * KVSPLIT * DD * DD];
__device__ float  g_ksp[BB * HH * KVSPLIT * DD];
__device__ float  g_part[(size_t)BNBLK * 2 * CC];
__device__ float  g_bp[BFSPLIT * K3];
__device__ float  g_a[CC], g_shift[CC], g_scale[CC];

// ---------------------------------------------------------------------------
// PTX helpers
// ---------------------------------------------------------------------------
__device__ __forceinline__ uint32_t smem_u32(const void* p) {
    uint32_t a;
    asm("{ .reg .u64 t; cvta.to.shared.u64 t, %1; cvt.u32.u64 %0, t; }" : "=r"(a) : "l"(p));
    return a;
}
__device__ __forceinline__ void cp_async16(uint32_t saddr, const void* gptr) {
    asm volatile("cp.async.cg.shared.global [%0], [%1], 16;" :: "r"(saddr), "l"(gptr) : "memory");
}
__device__ __forceinline__ void cp_commit() {
    asm volatile("cp.async.commit_group;" ::: "memory");
}
template <int N>
__device__ __forceinline__ void cp_wait() {
    asm volatile("cp.async.wait_group %0;" :: "n"(N) : "memory");
}
__device__ __forceinline__ void ldm_x4(uint32_t* r, uint32_t addr) {
    asm volatile("ldmatrix.sync.aligned.m8n8.x4.shared.b16 {%0,%1,%2,%3}, [%4];"
                 : "=r"(r[0]), "=r"(r[1]), "=r"(r[2]), "=r"(r[3]) : "r"(addr));
}
__device__ __forceinline__ void mma_f16(float* c, const uint32_t* a, const uint32_t* b) {
    asm volatile(
        "mma.sync.aligned.m16n8k16.row.col.f32.f16.f16.f32 "
        "{%0,%1,%2,%3}, {%4,%5,%6,%7}, {%8,%9}, {%0,%1,%2,%3};"
        : "+f"(c[0]), "+f"(c[1]), "+f"(c[2]), "+f"(c[3])
        : "r"(a[0]), "r"(a[1]), "r"(a[2]), "r"(a[3]), "r"(b[0]), "r"(b[1]));
}
// Packed f32x2 (Blackwell): one instruction, two fp32 FMAs
__device__ __forceinline__ void ffma2(uint64_t& c, uint64_t a, uint64_t b) {
    asm("fma.rn.f32x2 %0, %1, %2, %0;" : "+l"(c) : "l"(a), "l"(b));
}
__device__ __forceinline__ uint64_t pack2(float lo, float hi) {
    uint64_t r;
    asm("mov.b64 %0, {%1, %2};" : "=l"(r) : "f"(lo), "f"(hi));
    return r;
}
__device__ __forceinline__ float2 unpack2(uint64_t v) {
    float2 r;
    asm("mov.b64 {%0, %1}, %2;" : "=f"(r.x), "=f"(r.y) : "l"(v));
    return r;
}

// ---------------------------------------------------------------------------
// BN stats partial sums fused with x -> half conversion. 512 blocks x 32 rows.
// ---------------------------------------------------------------------------
__global__ void __launch_bounds__(256) bnf2h_kernel(const float* __restrict__ x,
                                                    __half* __restrict__ xh) {
    const int blk = blockIdx.x;
    const int tid = threadIdx.x;
    const int r0 = blk * 32;
    float s[4] = {0.f, 0.f, 0.f, 0.f};
    float ss[4] = {0.f, 0.f, 0.f, 0.f};
    for (int r = 0; r < 32; ++r) {
        const size_t rowo = (size_t)(r0 + r) * CC;
        float4 v = *(const float4*)(x + rowo + tid * 4);
        s[0] += v.x; ss[0] += v.x * v.x;
        s[1] += v.y; ss[1] += v.y * v.y;
        s[2] += v.z; ss[2] += v.z * v.z;
        s[3] += v.w; ss[3] += v.w * v.w;
        __half2 h0 = __floats2half2_rn(v.x, v.y);
        __half2 h1 = __floats2half2_rn(v.z, v.w);
        uint2 u;
        u.x = *(uint32_t*)&h0; u.y = *(uint32_t*)&h1;
        *(uint2*)(xh + rowo + tid * 4) = u;
    }
#pragma unroll
    for (int j = 0; j < 4; ++j) {
        g_part[(size_t)blk * 2048 + tid * 4 + j] = s[j];
        g_part[(size_t)blk * 2048 + 1024 + tid * 4 + j] = ss[j];
    }
}

__global__ void bn_finalize_kernel(const float* __restrict__ gamma,
                                   const float* __restrict__ beta,
                                   const float* __restrict__ scale_p) {
    const int ch = blockIdx.x * 256 + threadIdx.x;
    float s = 0.f, ss = 0.f;
    for (int b = 0; b < BNBLK; ++b) {
        s += g_part[(size_t)b * 2048 + ch];
        ss += g_part[(size_t)b * 2048 + 1024 + ch];
    }
    const float inv = 1.0f / (float)MM;
    float mean = s * inv;
    float var = ss * inv - mean * mean;
    float rstd = rsqrtf(var + 1e-5f);
    float a = rstd * gamma[ch];
    g_a[ch] = a;
    g_shift[ch] = beta[ch] - mean * a;
    float p = scale_p[ch];
    g_scale[ch] = fmaxf(p, 0.f) + log1pf(expf(-fabsf(p)));
}

// ---------------------------------------------------------------------------
// Prep (fused): z=0 -> transpose Wqkv with g_a folded -> g_whq
//               z=1 -> biasfold partials -> g_bp
//               z=2 -> transpose Wproj -> g_whp
// grid (96, 32, 3)
// ---------------------------------------------------------------------------
__global__ void __launch_bounds__(256) prep_kernel(const float* __restrict__ Wq,
                                                   const float* __restrict__ Wp) {
    __shared__ float t[32][33];
    const int tx = threadIdx.x & 31, ty = threadIdx.x >> 5;
    if (blockIdx.z == 0) {
        const int n0 = blockIdx.x * 32, k0 = blockIdx.y * 32;
#pragma unroll
        for (int i = 0; i < 4; ++i)
            t[ty + i * 8][tx] = Wq[(size_t)(k0 + ty + i * 8) * K3 + n0 + tx];
        __syncthreads();
        const float ak = g_a[k0 + tx];
#pragma unroll
        for (int i = 0; i < 4; ++i)
            g_whq[(size_t)(n0 + ty + i * 8) * CC + k0 + tx] =
                __float2half_rn(ak * t[tx][ty + i * 8]);
    } else if (blockIdx.z == 1) {
        if (blockIdx.x < 12 && blockIdx.y < 16) {
            const int n = blockIdx.x * 256 + threadIdx.x;
            const int k0 = blockIdx.y * (CC / BFSPLIT);
            float s = 0.f;
#pragma unroll 8
            for (int k = 0; k < CC / BFSPLIT; ++k)
                s += g_shift[k0 + k] * Wq[(size_t)(k0 + k) * K3 + n];
            g_bp[(size_t)blockIdx.y * K3 + n] = s;
        }
    } else {
        if (blockIdx.x < 32) {
            const int n0 = blockIdx.x * 32, k0 = blockIdx.y * 32;
#pragma unroll
            for (int i = 0; i < 4; ++i)
                t[ty + i * 8][tx] = Wp[(size_t)(k0 + ty + i * 8) * CC + n0 + tx];
            __syncthreads();
#pragma unroll
            for (int i = 0; i < 4; ++i)
                g_whp[(size_t)(n0 + ty + i * 8) * CC + k0 + tx] =
                    __float2half_rn(t[tx][ty + i * 8]);
        }
    }
}

// ---------------------------------------------------------------------------
// fp16 mma.sync GEMM. Block 128x128, BK=32, 8 warps (4m x 2n), warp 32x64,
// 5-stage ring, prefetch distance 3, barrier every 2 iterations.
// Fragment loads hoisted right after the barrier (LDSM/prefetch overlap).
// ---------------------------------------------------------------------------
template <bool SPLIT>
__global__ void __launch_bounds__(256, 2) gemm_hmma(
    const __half* __restrict__ A, const __half* __restrict__ Bt,
    const float* __restrict__ bias, float* __restrict__ Cf,
    int Ndim, int Kdim)
{
    extern __shared__ char sm[];
    const int tid = threadIdx.x;
    const int lane = tid & 31, w = tid >> 5;
    const int wm = w & 3, wn = w >> 2;
    const int row0 = blockIdx.y * 128, col0 = blockIdx.x * 128;
    const uint32_t sbase = smem_u32(sm);
    float* sbias = (float*)(sm + GEMM_SMEM5);

    if (SPLIT && tid < 128) {
        const int c = col0 + tid;
        float s = bias[c];
#pragma unroll
        for (int i = 0; i < BFSPLIT; ++i) s += g_bp[(size_t)i * K3 + c];
        sbias[tid] = s;
    }

    const int lrow = tid >> 1, lh = tid & 1;
    const __half* gA = A + (size_t)(row0 + lrow) * Kdim + lh * 16;
    const __half* gB = Bt + (size_t)(col0 + lrow) * Kdim + lh * 16;
    const uint32_t sOff = (uint32_t)(lrow * SSTRIDE + lh * 32);

    float acc[2][8][4];
#pragma unroll
    for (int mi = 0; mi < 2; ++mi)
#pragma unroll
        for (int ni = 0; ni < 8; ++ni)
#pragma unroll
            for (int j = 0; j < 4; ++j) acc[mi][ni][j] = 0.f;

    const uint32_t aoff0 = (uint32_t)((wm * 32 + (lane & 15)) * SSTRIDE + (lane >> 4) * 16);
    const uint32_t boff0 = (uint32_t)((wn * 64 + (lane & 7) + (lane >> 4) * 8) * SSTRIDE +
                                      ((lane >> 3) & 1) * 16);

    const int T = Kdim / BKH;   // even

    // prologue: stages 0..2
#pragma unroll
    for (int s = 0; s < 3; ++s) {
        const uint32_t sa = sbase + s * HSTAGE + sOff;
        const uint32_t sb = sa + HTILE;
        const __half* ga = gA + s * BKH;
        const __half* gb = gB + s * BKH;
        cp_async16(sa, ga);
        cp_async16(sa + 16, ga + 8);
        cp_async16(sb, gb);
        cp_async16(sb + 16, gb + 8);
        cp_commit();
    }

    for (int t = 0; t < T; t += 2) {
        cp_wait<1>();            // stages t and t+1 resident
        __syncthreads();

        const uint32_t a0base = sbase + (t % NSTG) * HSTAGE + aoff0;
        const uint32_t b0base = sbase + (t % NSTG) * HSTAGE + HTILE + boff0;
        const uint32_t a1base = sbase + ((t + 1) % NSTG) * HSTAGE + aoff0;
        const uint32_t b1base = sbase + ((t + 1) % NSTG) * HSTAGE + HTILE + boff0;

        uint32_t af[2][4];
        uint32_t bf[4][4];

        // --- iter t, ks=0: fragment loads first (overlap with prefetch issue) ---
#pragma unroll
        for (int mi = 0; mi < 2; ++mi) ldm_x4(af[mi], a0base + mi * 16 * SSTRIDE);
#pragma unroll
        for (int nt = 0; nt < 4; ++nt) ldm_x4(bf[nt], b0base + nt * 16 * SSTRIDE);

        if (t + 3 < T) {
            const int sidx = (t + 3) % NSTG;
            const uint32_t sa = sbase + sidx * HSTAGE + sOff;
            const uint32_t sb = sa + HTILE;
            const __half* ga = gA + (t + 3) * BKH;
            const __half* gb = gB + (t + 3) * BKH;
            cp_async16(sa, ga);
            cp_async16(sa + 16, ga + 8);
            cp_async16(sb, gb);
            cp_async16(sb + 16, gb + 8);
        }
        cp_commit();

#pragma unroll
        for (int mi = 0; mi < 2; ++mi)
#pragma unroll
            for (int ni = 0; ni < 8; ++ni)
                mma_f16(acc[mi][ni], af[mi], &bf[ni >> 1][(ni & 1) * 2]);

        // --- iter t, ks=1 ---
#pragma unroll
        for (int mi = 0; mi < 2; ++mi) ldm_x4(af[mi], a0base + mi * 16 * SSTRIDE + 32);
#pragma unroll
        for (int nt = 0; nt < 4; ++nt) ldm_x4(bf[nt], b0base + nt * 16 * SSTRIDE + 32);
#pragma unroll
        for (int mi = 0; mi < 2; ++mi)
#pragma unroll
            for (int ni = 0; ni < 8; ++ni)
                mma_f16(acc[mi][ni], af[mi], &bf[ni >> 1][(ni & 1) * 2]);

        // --- iter t+1, ks=0: loads can start during above MMAs (no barrier) ---
#pragma unroll
        for (int mi = 0; mi < 2; ++mi) ldm_x4(af[mi], a1base + mi * 16 * SSTRIDE);
#pragma unroll
        for (int nt = 0; nt < 4; ++nt) ldm_x4(bf[nt], b1base + nt * 16 * SSTRIDE);

        if (t + 4 < T) {
            const int sidx = (t + 4) % NSTG;
            const uint32_t sa = sbase + sidx * HSTAGE + sOff;
            const uint32_t sb = sa + HTILE;
            const __half* ga = gA + (t + 4) * BKH;
            const __half* gb = gB + (t + 4) * BKH;
            cp_async16(sa, ga);
            cp_async16(sa + 16, ga + 8);
            cp_async16(sb, gb);
            cp_async16(sb + 16, gb + 8);
        }
        cp_commit();

#pragma unroll
        for (int mi = 0; mi < 2; ++mi)
#pragma unroll
            for (int ni = 0; ni < 8; ++ni)
                mma_f16(acc[mi][ni], af[mi], &bf[ni >> 1][(ni & 1) * 2]);

        // --- iter t+1, ks=1 ---
#pragma unroll
        for (int mi = 0; mi < 2; ++mi) ldm_x4(af[mi], a1base + mi * 16 * SSTRIDE + 32);
#pragma unroll
        for (int nt = 0; nt < 4; ++nt) ldm_x4(bf[nt], b1base + nt * 16 * SSTRIDE + 32);
#pragma unroll
        for (int mi = 0; mi < 2; ++mi)
#pragma unroll
            for (int ni = 0; ni < 8; ++ni)
                mma_f16(acc[mi][ni], af[mi], &bf[ni >> 1][(ni & 1) * 2]);
    }
    __syncthreads();

    // epilogue
    const int lr = lane >> 2, lc = lane & 3;
    const float* brow = SPLIT ? (sbias + wn * 64) : (bias + col0 + wn * 64);

    if (!SPLIT) {
#pragma unroll
        for (int mi = 0; mi < 2; ++mi) {
            const int mrow = row0 + wm * 32 + mi * 16 + lr;
#pragma unroll
            for (int hf = 0; hf < 2; ++hf) {
                float* Cr = Cf + (size_t)(mrow + hf * 8) * Ndim + col0 + wn * 64;
#pragma unroll
                for (int ni = 0; ni < 8; ++ni) {
                    float2 o;
                    o.x = acc[mi][ni][hf * 2 + 0] + brow[ni * 8 + 2 * lc];
                    o.y = acc[mi][ni][hf * 2 + 1] + brow[ni * 8 + 2 * lc + 1];
                    *(float2*)(Cr + ni * 8 + 2 * lc) = o;
                }
            }
        }
    } else if (col0 >= QK2) {
        // v mode: plain half
#pragma unroll
        for (int mi = 0; mi < 2; ++mi) {
            const int mrow = row0 + wm * 32 + mi * 16 + lr;
#pragma unroll
            for (int hf = 0; hf < 2; ++hf) {
                __half* Hr = g_vh + (size_t)(mrow + hf * 8) * CC + (col0 - QK2) + wn * 64;
#pragma unroll
                for (int ni = 0; ni < 8; ++ni) {
                    float ox = acc[mi][ni][hf * 2 + 0] + brow[ni * 8 + 2 * lc];
                    float oy = acc[mi][ni][hf * 2 + 1] + brow[ni * 8 + 2 * lc + 1];
                    *(__half2*)(Hr + ni * 8 + 2 * lc) = __floats2half2_rn(ox, oy);
                }
            }
        }
    } else {
        // q/k focus mode: t = (relu(val)+1e-6)/scale; store t^3 as half + partials
        const int seg = (col0 >= CC) ? 1 : 0;
        const int colbase = (col0 - seg * CC) + wn * 64;
        const int slot = ((col0 - seg * CC) >> 7) * 2 + wn;   // 0..15
        __half* Hbase = seg ? g_kh : g_qh;
        float2* fpart = seg ? g_fk : g_fq;
#pragma unroll
        for (int mi = 0; mi < 2; ++mi) {
#pragma unroll
            for (int hf = 0; hf < 2; ++hf) {
                const int r = row0 + wm * 32 + mi * 16 + lr + hf * 8;
                __half* Hr = Hbase + (size_t)r * CC + colbase;
                float s2 = 0.f, s6 = 0.f;
#pragma unroll
                for (int ni = 0; ni < 8; ++ni) {
                    const int c = colbase + ni * 8 + 2 * lc;
                    float2 sc = *(const float2*)(g_scale + c);
                    float vx = acc[mi][ni][hf * 2 + 0] + brow[ni * 8 + 2 * lc];
                    float vy = acc[mi][ni][hf * 2 + 1] + brow[ni * 8 + 2 * lc + 1];
                    float tx = (fmaxf(vx, 0.f) + 1e-6f) / sc.x;
                    float ty = (fmaxf(vy, 0.f) + 1e-6f) / sc.y;
                    float tx2 = tx * tx, ty2 = ty * ty;
                    s2 += tx2 + ty2;
                    s6 += tx2 * tx2 * tx2 + ty2 * ty2 * ty2;
                    *(__half2*)(Hr + ni * 8 + 2 * lc) =
                        __floats2half2_rn(tx * tx2, ty * ty2);   // t^3
                }
                s2 += __shfl_xor_sync(0xffffffffu, s2, 1);
                s6 += __shfl_xor_sync(0xffffffffu, s6, 1);
                s2 += __shfl_xor_sync(0xffffffffu, s2, 2);
                s6 += __shfl_xor_sync(0xffffffffu, s6, 2);
                if (lc == 0)
                    fpart[(size_t)r * 16 + slot] = make_float2(s2, s6);
            }
        }
    }
}

// ---------------------------------------------------------------------------
// Per-row focus factor: r = sqrt(sum t^2) * rsqrt(sum t^6)
// ---------------------------------------------------------------------------
__global__ void __launch_bounds__(256) focus_finalize_kernel() {
    const int idx = blockIdx.x * 256 + threadIdx.x;   // 0..2*MM-1
    const int seg = idx >> 14;                        // MM = 2^14
    const int r = idx & (MM - 1);
    const float2* fp = (seg ? g_fk : g_fq) + (size_t)r * 16;
    float S2 = 0.f, S6 = 0.f;
#pragma unroll
    for (int i = 0; i < 16; ++i) {
        float2 v = fp[i];
        S2 += v.x; S6 += v.y;
    }
    g_r[idx] = sqrtf(S2) * rsqrtf(S6);
}

// ---------------------------------------------------------------------------
// Per-head partial kv = u_K^T V and ksum(u_K) over a slice of N.
// u = t3 * r_k[row] at smem fill (t3 already cubed); packed f32x2 FMA inner.
// grid (B*H, KVSPLIT) = (128, 16)
// ---------------------------------------------------------------------------
__global__ void __launch_bounds__(256) kv_part_kernel() {
    const int bh = blockIdx.x;
    const int chunk = blockIdx.y;
    const int b = bh >> 4, h = bh & 15;
    __shared__ float Ks[64][68];
    __shared__ float Vs[64][68];
    __shared__ float kred[4][64];
    const int tid = threadIdx.x;
    const int tr = tid >> 4, tc = tid & 15;
    const int lr = tid >> 4;
    const int lc4 = (tid & 15) * 4;

    uint64_t acc2[4][2];
#pragma unroll
    for (int i = 0; i < 4; ++i) { acc2[i][0] = 0ull; acc2[i][1] = 0ull; }
    float kpart = 0.f;
    const int scol = tid & 63, srg = tid >> 6;

    const int nlo = chunk * (NN / KVSPLIT);
    const int nhi = nlo + (NN / KVSPLIT);

    for (int n0 = nlo; n0 < nhi; n0 += 64) {
#pragma unroll
        for (int i = 0; i < 4; ++i) {
            const int r = lr + i * 16;
            const int grow = b * NN + n0 + r;
            const size_t off = (size_t)grow * CC + h * DD + lc4;
            const float rk = g_r[MM + grow];
            uint2 uk = *(const uint2*)(g_kh + off);
            uint2 uv = *(const uint2*)(g_vh + off);
            float2 k01 = __half22float2(*(__half2*)&uk.x);
            float2 k23 = __half22float2(*(__half2*)&uk.y);
            float2 v01 = __half22float2(*(__half2*)&uv.x);
            float2 v23 = __half22float2(*(__half2*)&uv.y);
            Ks[r][lc4 + 0] = k01.x * rk;
            Ks[r][lc4 + 1] = k01.y * rk;
            Ks[r][lc4 + 2] = k23.x * rk;
            Ks[r][lc4 + 3] = k23.y * rk;
            Vs[r][lc4 + 0] = v01.x; Vs[r][lc4 + 1] = v01.y;
            Vs[r][lc4 + 2] = v23.x; Vs[r][lc4 + 3] = v23.y;
        }
        __syncthreads();
#pragma unroll
        for (int kk = 0; kk < 64; ++kk) {
            float2 a01 = *(const float2*)&Ks[kk][tr * 4];
            float2 a23 = *(const float2*)&Ks[kk][tr * 4 + 2];
            float2 b01 = *(const float2*)&Vs[kk][tc * 4];
            float2 b23 = *(const float2*)&Vs[kk][tc * 4 + 2];
            const uint64_t bv0 = pack2(b01.x, b01.y);
            const uint64_t bv1 = pack2(b23.x, b23.y);
            const uint64_t a0 = pack2(a01.x, a01.x);
            const uint64_t a1 = pack2(a01.y, a01.y);
            const uint64_t a2 = pack2(a23.x, a23.x);
            const uint64_t a3 = pack2(a23.y, a23.y);
            ffma2(acc2[0][0], a0, bv0); ffma2(acc2[0][1], a0, bv1);
            ffma2(acc2[1][0], a1, bv0); ffma2(acc2[1][1], a1, bv1);
            ffma2(acc2[2][0], a2, bv0); ffma2(acc2[2][1], a2, bv1);
            ffma2(acc2[3][0], a3, bv0); ffma2(acc2[3][1], a3, bv1);
        }
#pragma unroll
        for (int r = 0; r < 16; ++r) kpart += Ks[srg * 16 + r][scol];
        __syncthreads();
    }
    kred[srg][scol] = kpart;
    __syncthreads();
    const size_t pb = (size_t)(bh * KVSPLIT + chunk);
    if (tid < 64)
        g_ksp[pb * DD + tid] = kred[0][tid] + kred[1][tid] + kred[2][tid] + kred[3][tid];
#pragma unroll
    for (int i = 0; i < 4; ++i) {
#pragma unroll
        for (int jp = 0; jp < 2; ++jp) {
            float2 u = unpack2(acc2[i][jp]);
            g_kvp[pb * 4096 + (tr * 4 + i) * 64 + tc * 4 + jp * 2 + 0] = u.x;
            g_kvp[pb * 4096 + (tr * 4 + i) * 64 + tc * 4 + jp * 2 + 1] = u.y;
        }
    }
}

__global__ void __launch_bounds__(256) kv_reduce_kernel() {
    const int bh = blockIdx.x;
    const int tid = threadIdx.x;
    for (int idx = tid; idx < 4096; idx += 256) {
        float s = 0.f;
#pragma unroll
        for (int c = 0; c < KVSPLIT; ++c)
            s += g_kvp[(size_t)(bh * KVSPLIT + c) * 4096 + idx];
        g_kv[(size_t)bh * 4096 + idx] = s;
    }
    if (tid < 64) {
        float s = 0.f;
#pragma unroll
        for (int c = 0; c < KVSPLIT; ++c)
            s += g_ksp[(size_t)(bh * KVSPLIT + c) * DD + tid];
        g_ksum[bh * DD + tid] = s;
    }
}

// ---------------------------------------------------------------------------
// Fused: o = (u_q @ kv) * z + depthwise-conv5(v) + dwc bias; writes half g_oh.
// u_q = t3 * r_q into smem once; f32x2 FMA inner loops, 2 rows per step.
// ---------------------------------------------------------------------------
__global__ void __launch_bounds__(256) o_dwc_kernel(const float* __restrict__ w,
                                                    const float* __restrict__ bias) {
    const int bh = blockIdx.y;
    const int b = bh >> 4, h = bh & 15;
    const int n0 = blockIdx.x * 64;
    __shared__ float qs[64][66];       // u_q tile
    __shared__ float2 kvf2[64][32];    // kv as column pairs
    __shared__ uint4 vsl4[68][8];      // v slice [n0-2, n0+66) x 64 ch (half)
    __shared__ float ks[64];
    const int tid = threadIdx.x;
    const int lane = tid & 31, warp = tid >> 5;

    for (int idx = tid; idx < 1024; idx += 256)
        ((uint4*)kvf2)[idx] = ((const uint4*)(g_kv + (size_t)bh * 4096))[idx];
    if (tid < 64) ks[tid] = g_ksum[bh * DD + tid];
    for (int idx = tid; idx < 68 * 8; idx += 256) {
        const int row = idx >> 3, seg = idx & 7;
        const int n = n0 - 2 + row;
        uint4 val = make_uint4(0u, 0u, 0u, 0u);
        if (n >= 0 && n < NN)
            val = *(const uint4*)(g_vh + (size_t)(b * NN + n) * CC + h * DD + seg * 8);
        vsl4[row][seg] = val;
    }
    for (int idx = tid; idx < 2048; idx += 256) {
        const int row = idx >> 5, c = idx & 31;
        const int gr = b * NN + n0 + row;
        const float rq = g_r[gr];
        __half2 hv = *(const __half2*)(g_qh + (size_t)gr * CC + h * DD + 2 * c);
        float2 t = __half22float2(hv);
        qs[row][2 * c + 0] = t.x * rq;
        qs[row][2 * c + 1] = t.y * rq;
    }
    __syncthreads();

    const __half* vsh = (const __half*)vsl4;   // [68][64]
    const int c0 = h * DD + 2 * lane;          // column pair base
    uint64_t wp[5];
#pragma unroll
    for (int j = 0; j < 5; ++j)
        wp[j] = pack2(w[c0 * KER + j], w[(c0 + 1) * KER + j]);
    const uint64_t bp = pack2(bias[c0], bias[c0 + 1]);
    const float2 ks2 = *(const float2*)&ks[2 * lane];

    for (int rr = 0; rr < 4; ++rr) {
        const int li0 = warp * 8 + rr * 2, li1 = li0 + 1;
        float2 q0p = *(const float2*)&qs[li0][2 * lane];
        float2 q1p = *(const float2*)&qs[li1][2 * lane];
        float zp0 = q0p.x * ks2.x + q0p.y * ks2.y;
        float zp1 = q1p.x * ks2.x + q1p.y * ks2.y;
#pragma unroll
        for (int o = 16; o; o >>= 1) {
            zp0 += __shfl_xor_sync(0xffffffffu, zp0, o);
            zp1 += __shfl_xor_sync(0xffffffffu, zp1, o);
        }
        const float z0 = 1.0f / (zp0 + 1e-6f);
        const float z1 = 1.0f / (zp1 + 1e-6f);

        uint64_t acc0 = 0ull, acc1 = 0ull;
#pragma unroll 16
        for (int d = 0; d < 64; ++d) {
            const float a0 = qs[li0][d];
            const float a1 = qs[li1][d];
            float2 kv = kvf2[d][lane];
            const uint64_t kvu = pack2(kv.x, kv.y);
            ffma2(acc0, pack2(a0, a0), kvu);
            ffma2(acc1, pack2(a1, a1), kvu);
        }

        uint64_t d0 = bp, d1 = bp;
#pragma unroll
        for (int j = 0; j < 5; ++j) {
            float2 v0 = __half22float2(*(const __half2*)(vsh + (li0 + j) * 64 + 2 * lane));
            float2 v1 = __half22float2(*(const __half2*)(vsh + (li1 + j) * 64 + 2 * lane));
            ffma2(d0, wp[j], pack2(v0.x, v0.y));
            ffma2(d1, wp[j], pack2(v1.x, v1.y));
        }

        float2 A0 = unpack2(acc0), A1 = unpack2(acc1);
        float2 D0 = unpack2(d0), D1 = unpack2(d1);
        __half* o0 = g_oh + (size_t)(b * NN + n0 + li0) * CC + c0;
        __half* o1 = g_oh + (size_t)(b * NN + n0 + li1) * CC + c0;
        *(__half2*)o0 = __floats2half2_rn(fmaf(A0.x, z0, D0.x), fmaf(A0.y, z0, D0.y));
        *(__half2*)o1 = __floats2half2_rn(fmaf(A1.x, z1, D1.x), fmaf(A1.y, z1, D1.y));
    }
}

// ---------------------------------------------------------------------------
// Launch (QKV GEMM is the 4th launch -> ncu capture slot)
// ---------------------------------------------------------------------------
extern "C" void kernel_launch(void* const* d_in, const int* in_sizes, int n_in,
                              void* d_out, int out_size) {
    const float* x       = (const float*)d_in[0];
    const float* gamma   = (const float*)d_in[1];
    const float* beta    = (const float*)d_in[2];
    const float* Wqkv    = (const float*)d_in[3];
    const float* bqkv    = (const float*)d_in[4];
    const float* scale_p = (const float*)d_in[5];
    const float* dwc_w   = (const float*)d_in[6];
    const float* dwc_b   = (const float*)d_in[7];
    const float* Wproj   = (const float*)d_in[8];
    const float* bproj   = (const float*)d_in[9];
    float* out = (float*)d_out;

    __half* xh_ptr;  cudaGetSymbolAddress((void**)&xh_ptr, g_xh);
    __half* whq_ptr; cudaGetSymbolAddress((void**)&whq_ptr, g_whq);
    __half* whp_ptr; cudaGetSymbolAddress((void**)&whp_ptr, g_whp);
    __half* oh_ptr;  cudaGetSymbolAddress((void**)&oh_ptr, g_oh);

    cudaFuncSetAttribute(gemm_hmma<true>,  cudaFuncAttributeMaxDynamicSharedMemorySize, GEMM_SMEM_TOT);
    cudaFuncSetAttribute(gemm_hmma<false>, cudaFuncAttributeMaxDynamicSharedMemorySize, GEMM_SMEM_TOT);

    // 1-2. BN statistics (fused with x -> half)
    bnf2h_kernel<<<BNBLK, 256>>>(x, xh_ptr);
    bn_finalize_kernel<<<4, 256>>>(gamma, beta, scale_p);

    // 3. Fused prep: Wqkv transpose (BN scale folded) + bias partials + Wproj transpose
    prep_kernel<<<dim3(96, 32, 3), 256>>>(Wqkv, Wproj);

    // 4. QKV GEMM (fused focus t^3 epilogue; bias built in smem from partials)
    gemm_hmma<true><<<dim3(K3 / 128, MM / 128), 256, GEMM_SMEM_TOT>>>(
        xh_ptr, whq_ptr, bqkv, (float*)nullptr, K3, CC);

    // 5. Per-row focus factors
    focus_finalize_kernel<<<2 * MM / 256, 256>>>();

    // 6-7. Per-head kv = u_K^T V and ksum (split over N, then reduce)
    kv_part_kernel<<<dim3(BB * HH, KVSPLIT), 256>>>();
    kv_reduce_kernel<<<BB * HH, 256>>>();

    // 8. Fused attention output + depthwise conv -> half g_oh
    o_dwc_kernel<<<dim3(NN / 64, BB * HH), 256>>>(dwc_w, dwc_b);

    // 9. Projection GEMM (f32 out)
    gemm_hmma<false><<<dim3(CC / 128, MM / 128), 256, GEMM_SMEM_TOT>>>(
        oh_ptr, whp_ptr, bproj, out, CC, CC);
}